// round 12
// baseline (speedup 1.0000x reference)
#include <cuda_runtime.h>
#include <cuda_bf16.h>
#include <cstdint>
#include <math.h>

#define Bn 8
#define Cn 256
#define Nn 4096

#define L2E 1.4426950408889634f
#define C2  72.134752f        // 50 * log2(e)

// ---------------------------------------------------------------------------
// Scratch
// ---------------------------------------------------------------------------
__device__ __nv_bfloat16 g_xqh[(size_t)Bn * Nn * Cn];  // queries^T hi [B,N,C]
__device__ __nv_bfloat16 g_xql[(size_t)Bn * Nn * Cn];
__device__ __nv_bfloat16 g_xkh[(size_t)Bn * Nn * Cn];  // keys^T hi [B,N,C]
__device__ __nv_bfloat16 g_xkl[(size_t)Bn * Nn * Cn];
__device__ __nv_bfloat16 g_wh[3 * Cn * Cn];            // Wq|Wk|Wv hi [O,C]
__device__ __nv_bfloat16 g_wl[3 * Cn * Cn];
__device__ __nv_bfloat16 g_qh[(size_t)Bn * Nn * Cn];   // q hi [B,N,C]
__device__ __nv_bfloat16 g_ql[(size_t)Bn * Nn * Cn];
__device__ __nv_bfloat16 g_kh[(size_t)Bn * Nn * Cn];   // k hi [B,N,C]
__device__ __nv_bfloat16 g_kl[(size_t)Bn * Nn * Cn];
__device__ __nv_bfloat16 g_vh[(size_t)Bn * Cn * Nn];   // v hi [B,C,N]
__device__ __nv_bfloat16 g_vl[(size_t)Bn * Cn * Nn];
__device__ __nv_bfloat16 g_Eh[(size_t)Bn * Nn * Nn];   // exp(s-50) hi [B,N,N]
__device__ __nv_bfloat16 g_El[(size_t)Bn * Nn * Nn];
__device__ float         g_Z [(size_t)Bn * Nn];        // row exp sums

// ---------------------------------------------------------------------------
// Helpers
// ---------------------------------------------------------------------------
__device__ __forceinline__ uint32_t smem_u32(const void* p) {
    uint32_t a;
    asm("{ .reg .u64 t; cvta.to.shared.u64 t, %1; cvt.u32.u64 %0, t; }"
        : "=r"(a) : "l"(p));
    return a;
}

#define SMEM_SWIZZLE_64B(off) ((off) ^ (((off) >> 3) & 0x30))

__device__ __forceinline__ void ldmx4(uint32_t* r, uint32_t a) {
    asm volatile("ldmatrix.sync.aligned.m8n8.x4.shared.b16 {%0,%1,%2,%3}, [%4];"
        : "=r"(r[0]), "=r"(r[1]), "=r"(r[2]), "=r"(r[3]) : "r"(a));
}

__device__ __forceinline__ void mma16816(float* d, const uint32_t* a,
                                         uint32_t b0, uint32_t b1) {
    asm volatile(
        "mma.sync.aligned.m16n8k16.row.col.f32.bf16.bf16.f32 "
        "{%0,%1,%2,%3}, {%4,%5,%6,%7}, {%8,%9}, {%0,%1,%2,%3};"
        : "+f"(d[0]), "+f"(d[1]), "+f"(d[2]), "+f"(d[3])
        : "r"(a[0]), "r"(a[1]), "r"(a[2]), "r"(a[3]), "r"(b0), "r"(b1));
}

__device__ __forceinline__ float ex2f(float x) {
    float y;
    asm("ex2.approx.f32 %0, %1;" : "=f"(y) : "f"(x));
    return y;
}

__device__ __forceinline__ uint32_t pack2(float a, float b, float& ra, float& rb) {
    __nv_bfloat16 ah = __float2bfloat16_rn(a);
    __nv_bfloat16 bh = __float2bfloat16_rn(b);
    ra = a - __bfloat162float(ah);
    rb = b - __bfloat162float(bh);
    __nv_bfloat162 t = __halves2bfloat162(ah, bh);
    return *reinterpret_cast<uint32_t*>(&t);
}

__device__ __forceinline__ uint32_t pack2lo(float a, float b) {
    __nv_bfloat162 t = __halves2bfloat162(__float2bfloat16_rn(a),
                                          __float2bfloat16_rn(b));
    return *reinterpret_cast<uint32_t*>(&t);
}

#define CP16(d, s) \
    asm volatile("cp.async.cg.shared.global [%0], [%1], 16;" :: "r"(d), "l"(s))
#define CP_COMMIT() asm volatile("cp.async.commit_group;" ::: "memory")
#define CP_WAIT1()  asm volatile("cp.async.wait_group 1;" ::: "memory")
#define CP_WAIT0()  asm volatile("cp.async.wait_group 0;" ::: "memory")

// ---------------------------------------------------------------------------
// GEMM building blocks: 3 stages x 4 tiles (Ah,Al,Bh,Bl) x 8KB = 96KB
// ---------------------------------------------------------------------------
#define TILE_B   8192
#define STAGE_B  (4 * TILE_B)
#define NSTAGES  3
#define MMA_SMEM (NSTAGES * STAGE_B)

__device__ __forceinline__ void cp_tile(uint32_t sdst, const __nv_bfloat16* g,
                                        int rs, int tid) {
    #pragma unroll
    for (int t = 0; t < 2; t++) {
        int u = tid + t * 256;
        int row = u >> 2, q = u & 3;
        uint32_t d = sdst + SMEM_SWIZZLE_64B((uint32_t)(row * 64 + q * 16));
        CP16(d, g + (size_t)row * rs + q * 8);
    }
}

__device__ __forceinline__ void prefetch4(uint32_t st,
                                          const __nv_bfloat16* ah,
                                          const __nv_bfloat16* al,
                                          const __nv_bfloat16* bh,
                                          const __nv_bfloat16* bl,
                                          int rsA, int rsB, int tid) {
    cp_tile(st + 0 * TILE_B, ah, rsA, tid);
    cp_tile(st + 1 * TILE_B, al, rsA, tid);
    cp_tile(st + 2 * TILE_B, bh, rsB, tid);
    cp_tile(st + 3 * TILE_B, bl, rsB, tid);
    CP_COMMIT();
}

// One K=32 chunk of MMAs (product-major, 2-way bf16 split: hh+hl+lh).
__device__ __forceinline__ void chunk_mma(uint32_t tb, uint32_t aoff,
                                          uint32_t boff, uint32_t lsw,
                                          float acc[4][4][4]) {
    #pragma unroll
    for (int ks = 0; ks < 2; ks++) {
        uint32_t kb = (uint32_t)(ks * 32);
        uint32_t ah[4][4], al[4][4];
        #pragma unroll
        for (int it = 0; it < 4; it++) {
            uint32_t o = (aoff + it * 1024 + kb) ^ lsw;
            ldmx4(ah[it], tb + o);
            ldmx4(al[it], tb + TILE_B + o);
        }
        uint32_t bh[4][2], bl[4][2];
        #pragma unroll
        for (int jp = 0; jp < 2; jp++) {
            uint32_t o = (boff + jp * 1024 + kb) ^ lsw;
            uint32_t t4[4];
            ldmx4(t4, tb + 2 * TILE_B + o);
            bh[jp * 2][0]     = t4[0]; bh[jp * 2][1]     = t4[2];
            bh[jp * 2 + 1][0] = t4[1]; bh[jp * 2 + 1][1] = t4[3];
            ldmx4(t4, tb + 3 * TILE_B + o);
            bl[jp * 2][0]     = t4[0]; bl[jp * 2][1]     = t4[2];
            bl[jp * 2 + 1][0] = t4[1]; bl[jp * 2 + 1][1] = t4[3];
        }
        #pragma unroll
        for (int it = 0; it < 4; it++)
            #pragma unroll
            for (int nt = 0; nt < 4; nt++)
                mma16816(acc[it][nt], ah[it], bh[nt][0], bh[nt][1]);
        #pragma unroll
        for (int it = 0; it < 4; it++)
            #pragma unroll
            for (int nt = 0; nt < 4; nt++)
                mma16816(acc[it][nt], ah[it], bl[nt][0], bl[nt][1]);
        #pragma unroll
        for (int it = 0; it < 4; it++)
            #pragma unroll
            for (int nt = 0; nt < 4; nt++)
                mma16816(acc[it][nt], al[it], bh[nt][0], bh[nt][1]);
    }
}

// Plain (non-chained) mainloop for pv.
__device__ __forceinline__ void mma_mainloop(
    uint32_t sbase,
    const __nv_bfloat16* Ah, const __nv_bfloat16* Al,
    const __nv_bfloat16* Bh, const __nv_bfloat16* Bl,
    int rsA, int rsB, int nch,
    float acc[4][4][4], int tid, int wid, int lane)
{
    const int iBase = (wid >> 2) * 64;
    const int jBase = (wid & 3) * 32;
    const uint32_t lsw  = (uint32_t)(((lane >> 1) & 3) * 16);
    const uint32_t aoff = (uint32_t)((iBase + (lane & 15)) * 64 + (lane >> 4) * 16);
    const uint32_t boff = (uint32_t)((jBase + (lane & 15)) * 64 + (lane >> 4) * 16);

    #pragma unroll
    for (int p = 0; p < 2; p++)
        prefetch4(sbase + p * STAGE_B, Ah + p * 32, Al + p * 32,
                  Bh + p * 32, Bl + p * 32, rsA, rsB, tid);

    int stage = 0;
    #pragma unroll 1
    for (int c = 0; c < nch; c++) {
        if (c + 1 < nch) CP_WAIT1(); else CP_WAIT0();
        __syncthreads();
        if (c + 2 < nch) {
            int ps = stage + 2; if (ps >= NSTAGES) ps -= NSTAGES;
            int ko = (c + 2) * 32;
            prefetch4(sbase + ps * STAGE_B, Ah + ko, Al + ko,
                      Bh + ko, Bl + ko, rsA, rsB, tid);
        }
        chunk_mma(sbase + stage * STAGE_B, aoff, boff, lsw, acc);
        if (++stage == NSTAGES) stage = 0;
    }
}

// ---------------------------------------------------------------------------
// Kernel A: transpose + bf16 hi/lo split.  x [B,C,N] fp32 -> out [B,N,C].
// ---------------------------------------------------------------------------
__global__ void __launch_bounds__(256)
conv_split(const float* __restrict__ x,
           __nv_bfloat16* __restrict__ oh,
           __nv_bfloat16* __restrict__ ol) {
    __shared__ float ts[32][33];
    const int b = blockIdx.z, c0 = blockIdx.y * 32, n0 = blockIdx.x * 32;
    const int r = threadIdx.x >> 5, col = threadIdx.x & 31;

    const float* xb = x + ((size_t)b * Cn + c0) * Nn + n0;
    #pragma unroll
    for (int p = 0; p < 4; p++)
        ts[r + p * 8][col] = xb[(size_t)(r + p * 8) * Nn + col];
    __syncthreads();

    __nv_bfloat16* dh = oh + ((size_t)b * Nn + n0) * Cn + c0;
    __nv_bfloat16* dl = ol + ((size_t)b * Nn + n0) * Cn + c0;
    #pragma unroll
    for (int p = 0; p < 4; p++) {
        int n = r + p * 8;
        float f = ts[col][n];
        __nv_bfloat16 h = __float2bfloat16_rn(f);
        dh[(size_t)n * Cn + col] = h;
        dl[(size_t)n * Cn + col] = __float2bfloat16_rn(f - __bfloat162float(h));
    }
}

// ---------------------------------------------------------------------------
// Kernel B: split W matrices (768 blocks) + zero Z (128 blocks).
// ---------------------------------------------------------------------------
__global__ void __launch_bounds__(256)
wsplit_zero(const float* __restrict__ Wq, const float* __restrict__ Wk,
            const float* __restrict__ Wv) {
    int bid = blockIdx.x;
    if (bid < 768) {
        int idx = bid * 256 + threadIdx.x;
        int which = idx >> 16, off = idx & 65535;
        const float* s = (which == 0) ? Wq : (which == 1) ? Wk : Wv;
        float f = s[off];
        __nv_bfloat16 h = __float2bfloat16_rn(f);
        g_wh[idx] = h;
        g_wl[idx] = __float2bfloat16_rn(f - __bfloat162float(h));
    } else {
        g_Z[(size_t)(bid - 768) * 256 + threadIdx.x] = 0.f;
    }
}

// ---------------------------------------------------------------------------
// Kernel C1: projection -> [N, C] (q, k). CHAINED over 2 o-tiles (o = 0, 128).
// out[n,o] = sum_c xT[n,c] * W[o,c] + bias[o].  Grid (1, 32, 8) = 256 CTAs.
// ---------------------------------------------------------------------------
__global__ void __launch_bounds__(256, 2)
proj_nk(const __nv_bfloat16* __restrict__ xh, const __nv_bfloat16* __restrict__ xl,
        const __nv_bfloat16* __restrict__ wh, const __nv_bfloat16* __restrict__ wl,
        const float* __restrict__ bias,
        __nv_bfloat16* __restrict__ oh, __nv_bfloat16* __restrict__ ol) {
    extern __shared__ char smem[];
    uint32_t sbase = smem_u32(smem);
    const int tid = threadIdx.x;
    const int wid = tid >> 5, lane = tid & 31;

    const int b  = blockIdx.z;
    const int n0 = blockIdx.y * 128;

    const __nv_bfloat16* Ah = xh + ((size_t)b * Nn + n0) * Cn;
    const __nv_bfloat16* Al = xl + ((size_t)b * Nn + n0) * Cn;

    const int iBase = (wid >> 2) * 64;
    const int jBase = (wid & 3) * 32;
    const uint32_t lsw  = (uint32_t)(((lane >> 1) & 3) * 16);
    const uint32_t aoff = (uint32_t)((iBase + (lane & 15)) * 64 + (lane >> 4) * 16);
    const uint32_t boff = (uint32_t)((jBase + (lane & 15)) * 64 + (lane >> 4) * 16);
    const int g_ = lane >> 2, cp2 = (lane & 3) * 2;

    __nv_bfloat16* dh = oh + (size_t)b * Nn * Cn;
    __nv_bfloat16* dl = ol + (size_t)b * Nn * Cn;

    float acc[4][4][4] = {};

    const int G = 16;  // 2 tiles x 8 chunks
    #pragma unroll
    for (int p = 0; p < 2; p++)
        prefetch4(sbase + p * STAGE_B, Ah + p * 32, Al + p * 32,
                  wh + p * 32, wl + p * 32, Cn, Cn, tid);

    int stage = 0;
    #pragma unroll 1
    for (int g = 0; g < G; g++) {
        if (g + 1 < G) CP_WAIT1(); else CP_WAIT0();
        __syncthreads();
        if (g + 2 < G) {
            int ps = stage + 2; if (ps >= NSTAGES) ps -= NSTAGES;
            int gg = g + 2;
            int kc = (gg & 7) * 32;
            size_t bo = (size_t)(gg >> 3) * 128 * Cn + kc;
            prefetch4(sbase + ps * STAGE_B, Ah + kc, Al + kc,
                      wh + bo, wl + bo, Cn, Cn, tid);
        }
        chunk_mma(sbase + stage * STAGE_B, aoff, boff, lsw, acc);
        if (++stage == NSTAGES) stage = 0;

        if ((g & 7) == 7) {
            int o0 = (g >> 3) * 128;
            #pragma unroll
            for (int nt = 0; nt < 4; nt++) {
                int cc = o0 + jBase + nt * 8 + cp2;
                float b0 = bias[cc], b1 = bias[cc + 1];
                #pragma unroll
                for (int it = 0; it < 4; it++) {
                    int r1 = n0 + iBase + it * 16 + g_;
                    float l0, l1;
                    uint32_t h01 = pack2(acc[it][nt][0] + b0, acc[it][nt][1] + b1, l0, l1);
                    *reinterpret_cast<uint32_t*>(&dh[(size_t)r1 * Cn + cc]) = h01;
                    *reinterpret_cast<uint32_t*>(&dl[(size_t)r1 * Cn + cc]) = pack2lo(l0, l1);
                    uint32_t h23 = pack2(acc[it][nt][2] + b0, acc[it][nt][3] + b1, l0, l1);
                    *reinterpret_cast<uint32_t*>(&dh[(size_t)(r1 + 8) * Cn + cc]) = h23;
                    *reinterpret_cast<uint32_t*>(&dl[(size_t)(r1 + 8) * Cn + cc]) = pack2lo(l0, l1);
                }
            }
            #pragma unroll
            for (int it = 0; it < 4; it++)
                #pragma unroll
                for (int nt = 0; nt < 4; nt++)
                    #pragma unroll
                    for (int k = 0; k < 4; k++)
                        acc[it][nt][k] = 0.f;
        }
    }
}

// ---------------------------------------------------------------------------
// Kernel C2: projection -> [C, N] (v). CHAINED over 2 n-tiles.
// out[o,n] = sum_c W[o,c] * xT[n,c] + bias[o].  Grid (16, 2, 8) = 256 CTAs.
// ---------------------------------------------------------------------------
__global__ void __launch_bounds__(256, 2)
proj_cn(const __nv_bfloat16* __restrict__ wh, const __nv_bfloat16* __restrict__ wl,
        const __nv_bfloat16* __restrict__ xh, const __nv_bfloat16* __restrict__ xl,
        const float* __restrict__ bias,
        __nv_bfloat16* __restrict__ oh, __nv_bfloat16* __restrict__ ol) {
    extern __shared__ char smem[];
    uint32_t sbase = smem_u32(smem);
    const int tid = threadIdx.x;
    const int wid = tid >> 5, lane = tid & 31;

    const int b   = blockIdx.z;
    const int o0  = blockIdx.y * 128;
    const int n00 = blockIdx.x * 256;

    const __nv_bfloat16* Ah = wh + (size_t)o0 * Cn;
    const __nv_bfloat16* Al = wl + (size_t)o0 * Cn;
    const __nv_bfloat16* Bh0 = xh + ((size_t)b * Nn + n00) * Cn;
    const __nv_bfloat16* Bl0 = xl + ((size_t)b * Nn + n00) * Cn;

    const int iBase = (wid >> 2) * 64;
    const int jBase = (wid & 3) * 32;
    const uint32_t lsw  = (uint32_t)(((lane >> 1) & 3) * 16);
    const uint32_t aoff = (uint32_t)((iBase + (lane & 15)) * 64 + (lane >> 4) * 16);
    const uint32_t boff = (uint32_t)((jBase + (lane & 15)) * 64 + (lane >> 4) * 16);
    const int g_ = lane >> 2, cp2 = (lane & 3) * 2;

    __nv_bfloat16* dh = oh + (size_t)b * Cn * Nn;
    __nv_bfloat16* dl = ol + (size_t)b * Cn * Nn;

    float acc[4][4][4] = {};

    const int G = 16;
    #pragma unroll
    for (int p = 0; p < 2; p++)
        prefetch4(sbase + p * STAGE_B, Ah + p * 32, Al + p * 32,
                  Bh0 + p * 32, Bl0 + p * 32, Cn, Cn, tid);

    int stage = 0;
    #pragma unroll 1
    for (int g = 0; g < G; g++) {
        if (g + 1 < G) CP_WAIT1(); else CP_WAIT0();
        __syncthreads();
        if (g + 2 < G) {
            int ps = stage + 2; if (ps >= NSTAGES) ps -= NSTAGES;
            int gg = g + 2;
            int kc = (gg & 7) * 32;
            size_t bo = (size_t)(gg >> 3) * 128 * Cn + kc;
            prefetch4(sbase + ps * STAGE_B, Ah + kc, Al + kc,
                      Bh0 + bo, Bl0 + bo, Cn, Cn, tid);
        }
        chunk_mma(sbase + stage * STAGE_B, aoff, boff, lsw, acc);
        if (++stage == NSTAGES) stage = 0;

        if ((g & 7) == 7) {
            int n0 = n00 + (g >> 3) * 128;
            #pragma unroll
            for (int it = 0; it < 4; it++) {
                int r1 = o0 + iBase + it * 16 + g_;
                float br1 = bias[r1], br2 = bias[r1 + 8];
                #pragma unroll
                for (int nt = 0; nt < 4; nt++) {
                    int cc = n0 + jBase + nt * 8 + cp2;
                    float l0, l1;
                    uint32_t h01 = pack2(acc[it][nt][0] + br1, acc[it][nt][1] + br1, l0, l1);
                    *reinterpret_cast<uint32_t*>(&dh[(size_t)r1 * Nn + cc]) = h01;
                    *reinterpret_cast<uint32_t*>(&dl[(size_t)r1 * Nn + cc]) = pack2lo(l0, l1);
                    uint32_t h23 = pack2(acc[it][nt][2] + br2, acc[it][nt][3] + br2, l0, l1);
                    *reinterpret_cast<uint32_t*>(&dh[(size_t)(r1 + 8) * Nn + cc]) = h23;
                    *reinterpret_cast<uint32_t*>(&dl[(size_t)(r1 + 8) * Nn + cc]) = pack2lo(l0, l1);
                }
            }
            #pragma unroll
            for (int it = 0; it < 4; it++)
                #pragma unroll
                for (int nt = 0; nt < 4; nt++)
                    #pragma unroll
                    for (int k = 0; k < 4; k++)
                        acc[it][nt][k] = 0.f;
        }
    }
}

// ---------------------------------------------------------------------------
// Kernel D: scores. CHAINED over 4 j-tiles (j = j00 .. j00+512).
// Epilogue stores E = exp(s-50) bf16 hi/lo + Z partial sums.
// Grid (8, 32, 8) = 2048 CTAs.
// ---------------------------------------------------------------------------
__global__ void __launch_bounds__(256, 2)
scores_mma(const float* __restrict__ mask) {
    extern __shared__ char smem[];
    uint32_t sbase = smem_u32(smem);
    const int tid = threadIdx.x;
    const int wid = tid >> 5, lane = tid & 31;

    const int b   = blockIdx.z;
    const int i0  = blockIdx.y * 128;
    const int j00 = blockIdx.x * 512;

    const __nv_bfloat16* Ah = g_qh + ((size_t)b * Nn + i0) * Cn;
    const __nv_bfloat16* Al = g_ql + ((size_t)b * Nn + i0) * Cn;
    const __nv_bfloat16* Bh0 = g_kh + ((size_t)b * Nn + j00) * Cn;
    const __nv_bfloat16* Bl0 = g_kl + ((size_t)b * Nn + j00) * Cn;

    const int iBase = (wid >> 2) * 64;
    const int jBase = (wid & 3) * 32;
    const uint32_t lsw  = (uint32_t)(((lane >> 1) & 3) * 16);
    const uint32_t aoff = (uint32_t)((iBase + (lane & 15)) * 64 + (lane >> 4) * 16);
    const uint32_t boff = (uint32_t)((jBase + (lane & 15)) * 64 + (lane >> 4) * 16);
    const int g_ = lane >> 2, cp2 = (lane & 3) * 2;

    const float* mb = mask + (size_t)b * Nn;
    __nv_bfloat16* Ehb = g_Eh + (size_t)b * Nn * Nn;
    __nv_bfloat16* Elb = g_El + (size_t)b * Nn * Nn;
    float* Zb = g_Z + (size_t)b * Nn;

    float acc[4][4][4] = {};

    const int G = 32;  // 4 tiles x 8 chunks
    #pragma unroll
    for (int p = 0; p < 2; p++)
        prefetch4(sbase + p * STAGE_B, Ah + p * 32, Al + p * 32,
                  Bh0 + p * 32, Bl0 + p * 32, Cn, Cn, tid);

    int stage = 0;
    #pragma unroll 1
    for (int g = 0; g < G; g++) {
        if (g + 1 < G) CP_WAIT1(); else CP_WAIT0();
        __syncthreads();
        if (g + 2 < G) {
            int ps = stage + 2; if (ps >= NSTAGES) ps -= NSTAGES;
            int gg = g + 2;
            int kc = (gg & 7) * 32;
            size_t bo = (size_t)(gg >> 3) * 128 * Cn + kc;
            prefetch4(sbase + ps * STAGE_B, Ah + kc, Al + kc,
                      Bh0 + bo, Bl0 + bo, Cn, Cn, tid);
        }
        chunk_mma(sbase + stage * STAGE_B, aoff, boff, lsw, acc);
        if (++stage == NSTAGES) stage = 0;

        if ((g & 7) == 7) {
            int j0 = j00 + (g >> 3) * 128;
            #pragma unroll
            for (int it = 0; it < 4; it++) {
                int r1 = i0 + iBase + it * 16 + g_;
                float m1 = mb[r1], m2 = mb[r1 + 8];
                float z1 = 0.f, z2 = 0.f;
                #pragma unroll
                for (int nt = 0; nt < 4; nt++) {
                    int cc = j0 + jBase + nt * 8 + cp2;
                    float e0 = ex2f(fmaf(acc[it][nt][0] * m1, L2E, -C2));
                    float e1 = ex2f(fmaf(acc[it][nt][1] * m1, L2E, -C2));
                    float e2 = ex2f(fmaf(acc[it][nt][2] * m2, L2E, -C2));
                    float e3 = ex2f(fmaf(acc[it][nt][3] * m2, L2E, -C2));
                    z1 += e0 + e1;
                    z2 += e2 + e3;
                    float l0, l1;
                    uint32_t h01 = pack2(e0, e1, l0, l1);
                    *reinterpret_cast<uint32_t*>(&Ehb[(size_t)r1 * Nn + cc]) = h01;
                    *reinterpret_cast<uint32_t*>(&Elb[(size_t)r1 * Nn + cc]) = pack2lo(l0, l1);
                    uint32_t h23 = pack2(e2, e3, l0, l1);
                    *reinterpret_cast<uint32_t*>(&Ehb[(size_t)(r1 + 8) * Nn + cc]) = h23;
                    *reinterpret_cast<uint32_t*>(&Elb[(size_t)(r1 + 8) * Nn + cc]) = pack2lo(l0, l1);
                }
                z1 += __shfl_xor_sync(0xffffffffu, z1, 1);
                z1 += __shfl_xor_sync(0xffffffffu, z1, 2);
                z2 += __shfl_xor_sync(0xffffffffu, z2, 1);
                z2 += __shfl_xor_sync(0xffffffffu, z2, 2);
                if ((lane & 3) == 0) {
                    atomicAdd(&Zb[r1], z1);
                    atomicAdd(&Zb[r1 + 8], z2);
                }
            }
            #pragma unroll
            for (int it = 0; it < 4; it++)
                #pragma unroll
                for (int nt = 0; nt < 4; nt++)
                    #pragma unroll
                    for (int k = 0; k < 4; k++)
                        acc[it][nt][k] = 0.f;
        }
    }
}

// ---------------------------------------------------------------------------
// Kernel E: PV GEMM on unnormalized E + normalize/blend epilogue.
// ---------------------------------------------------------------------------
__global__ void __launch_bounds__(256, 2)
pv_mma(const float* __restrict__ mask,
       const float* __restrict__ queries,
       float* __restrict__ out) {
    extern __shared__ char smem[];
    uint32_t sbase = smem_u32(smem);
    const int tid = threadIdx.x;
    const int wid = tid >> 5, lane = tid & 31;

    const int b  = blockIdx.z;
    const int c0 = blockIdx.y * 128;
    const int q0 = blockIdx.x * 128;

    float acc[4][4][4] = {};
    mma_mainloop(sbase,
                 g_vh + ((size_t)b * Cn + c0) * Nn, g_vl + ((size_t)b * Cn + c0) * Nn,
                 g_Eh + ((size_t)b * Nn + q0) * Nn, g_El + ((size_t)b * Nn + q0) * Nn,
                 Nn, Nn, Nn / 32, acc, tid, wid, lane);

    const int iBase = (wid >> 2) * 64;
    const int jBase = (wid & 3) * 32;
    const int g = lane >> 2, cp2 = (lane & 3) * 2;
    const float* mb = mask + (size_t)b * Nn;
    const float* Zb = g_Z + (size_t)b * Nn;

    int   qc[4];
    float m0[4], m1[4], iz0[4], iz1[4];
    #pragma unroll
    for (int nt = 0; nt < 4; nt++) {
        qc[nt] = q0 + jBase + nt * 8 + cp2;
        m0[nt] = mb[qc[nt]];
        m1[nt] = mb[qc[nt] + 1];
        iz0[nt] = __fdividef(1.f, Zb[qc[nt]]);
        iz1[nt] = __fdividef(1.f, Zb[qc[nt] + 1]);
    }

    #pragma unroll
    for (int it = 0; it < 4; it++) {
        int cr = c0 + iBase + it * 16 + g;
        #pragma unroll
        for (int nt = 0; nt < 4; nt++) {
            size_t gi1 = ((size_t)b * Cn + cr) * Nn + qc[nt];
            size_t gi2 = gi1 + (size_t)8 * Nn;
            float2 qa = *reinterpret_cast<const float2*>(&queries[gi1]);
            float2 qb = *reinterpret_cast<const float2*>(&queries[gi2]);
            float2 o1, o2;
            o1.x = qa.x * m0[nt] + (1.f - m0[nt]) * acc[it][nt][0] * iz0[nt];
            o1.y = qa.y * m1[nt] + (1.f - m1[nt]) * acc[it][nt][1] * iz1[nt];
            o2.x = qb.x * m0[nt] + (1.f - m0[nt]) * acc[it][nt][2] * iz0[nt];
            o2.y = qb.y * m1[nt] + (1.f - m1[nt]) * acc[it][nt][3] * iz1[nt];
            *reinterpret_cast<float2*>(&out[gi1]) = o1;
            *reinterpret_cast<float2*>(&out[gi2]) = o2;
        }
    }
}

// ---------------------------------------------------------------------------
// Launch
// ---------------------------------------------------------------------------
extern "C" void kernel_launch(void* const* d_in, const int* in_sizes, int n_in,
                              void* d_out, int out_size) {
    const float* queries = (const float*)d_in[0];
    const float* keys    = (const float*)d_in[1];
    const float* mask    = (const float*)d_in[2];
    const float* Wq      = (const float*)d_in[3];
    const float* bq      = (const float*)d_in[4];
    const float* Wk      = (const float*)d_in[5];
    const float* bk      = (const float*)d_in[6];
    const float* Wv      = (const float*)d_in[7];
    const float* bv      = (const float*)d_in[8];
    float* out = (float*)d_out;

    cudaFuncSetAttribute(proj_nk,    cudaFuncAttributeMaxDynamicSharedMemorySize, MMA_SMEM);
    cudaFuncSetAttribute(proj_cn,    cudaFuncAttributeMaxDynamicSharedMemorySize, MMA_SMEM);
    cudaFuncSetAttribute(scores_mma, cudaFuncAttributeMaxDynamicSharedMemorySize, MMA_SMEM);
    cudaFuncSetAttribute(pv_mma,     cudaFuncAttributeMaxDynamicSharedMemorySize, MMA_SMEM);

    __nv_bfloat16 *xqh, *xql, *xkh, *xkl, *wh, *wl, *qh, *ql, *kh, *kl, *vh, *vl;
    cudaGetSymbolAddress((void**)&xqh, g_xqh);
    cudaGetSymbolAddress((void**)&xql, g_xql);
    cudaGetSymbolAddress((void**)&xkh, g_xkh);
    cudaGetSymbolAddress((void**)&xkl, g_xkl);
    cudaGetSymbolAddress((void**)&wh,  g_wh);
    cudaGetSymbolAddress((void**)&wl,  g_wl);
    cudaGetSymbolAddress((void**)&qh,  g_qh);
    cudaGetSymbolAddress((void**)&ql,  g_ql);
    cudaGetSymbolAddress((void**)&kh,  g_kh);
    cudaGetSymbolAddress((void**)&kl,  g_kl);
    cudaGetSymbolAddress((void**)&vh,  g_vh);
    cudaGetSymbolAddress((void**)&vl,  g_vl);

    // Input transpose + split
    dim3 gcv(Nn / 32, Cn / 32, Bn);
    conv_split<<<gcv, 256>>>(queries, xqh, xql);
    conv_split<<<gcv, 256>>>(keys,    xkh, xkl);
    wsplit_zero<<<896, 256>>>(Wq, Wk, Wv);

    // Projections via HMMA (chained tiles)
    dim3 gnk(1, Nn / 128, Bn);
    proj_nk<<<gnk, 256, MMA_SMEM>>>(xqh, xql, wh,           wl,           bq, qh, ql);
    proj_nk<<<gnk, 256, MMA_SMEM>>>(xkh, xkl, wh + Cn * Cn, wl + Cn * Cn, bk, kh, kl);
    dim3 gcn(Nn / 256, Cn / 128, Bn);
    proj_cn<<<gcn, 256, MMA_SMEM>>>(wh + 2 * Cn * Cn, wl + 2 * Cn * Cn, xkh, xkl, bv, vh, vl);

    // Scores -> E (unnormalized exp) + Z  (chained 4 j-tiles per CTA)
    dim3 gsc(Nn / 512, Nn / 128, Bn);
    scores_mma<<<gsc, 256, MMA_SMEM>>>(mask);

    // PV + normalize + blend
    dim3 gpv(Nn / 128, Cn / 128, Bn);
    pv_mma<<<gpv, 256, MMA_SMEM>>>(mask, queries, out);
}

// round 13
// speedup vs baseline: 1.0396x; 1.0396x over previous
#include <cuda_runtime.h>
#include <cuda_bf16.h>
#include <cstdint>
#include <math.h>

#define Bn 8
#define Cn 256
#define Nn 4096

#define L2E 1.4426950408889634f
#define C2  72.134752f        // 50 * log2(e)

// ---------------------------------------------------------------------------
// Scratch
// ---------------------------------------------------------------------------
__device__ __nv_bfloat16 g_xqh[(size_t)Bn * Nn * Cn];  // queries^T hi [B,N,C]
__device__ __nv_bfloat16 g_xql[(size_t)Bn * Nn * Cn];
__device__ __nv_bfloat16 g_xkh[(size_t)Bn * Nn * Cn];  // keys^T hi [B,N,C]
__device__ __nv_bfloat16 g_xkl[(size_t)Bn * Nn * Cn];
__device__ __nv_bfloat16 g_Mh[Cn * Cn];                // M = Wq^T Wk  [c][d]
__device__ __nv_bfloat16 g_Ml[Cn * Cn];
__device__ __nv_bfloat16 g_wvh[Cn * Cn];               // Wv hi [O,C]
__device__ __nv_bfloat16 g_wvl[Cn * Cn];
__device__ __nv_bfloat16 g_yh[(size_t)Bn * Nn * Cn];   // y = M xk  [B,N,C]
__device__ __nv_bfloat16 g_yl[(size_t)Bn * Nn * Cn];
__device__ __nv_bfloat16 g_vh[(size_t)Bn * Cn * Nn];   // v hi [B,C,N]
__device__ __nv_bfloat16 g_vl[(size_t)Bn * Cn * Nn];
__device__ __nv_bfloat16 g_Eh[(size_t)Bn * Nn * Nn];   // exp(s-50) hi [B,N,N]
__device__ __nv_bfloat16 g_El[(size_t)Bn * Nn * Nn];
__device__ float         g_Z [(size_t)Bn * Nn];        // row exp sums
__device__ float         g_abw[513];                   // aw[256] | bw[256] | cc
__device__ float         g_alpha[(size_t)Bn * Nn];     // per-j bias term (+cc)
__device__ float         g_beta [(size_t)Bn * Nn];     // per-i bias term
__device__ float         g_bzero[Cn];                  // zero bias

// ---------------------------------------------------------------------------
// Helpers
// ---------------------------------------------------------------------------
__device__ __forceinline__ uint32_t smem_u32(const void* p) {
    uint32_t a;
    asm("{ .reg .u64 t; cvta.to.shared.u64 t, %1; cvt.u32.u64 %0, t; }"
        : "=r"(a) : "l"(p));
    return a;
}

#define SMEM_SWIZZLE_64B(off) ((off) ^ (((off) >> 3) & 0x30))

__device__ __forceinline__ void ldmx4(uint32_t* r, uint32_t a) {
    asm volatile("ldmatrix.sync.aligned.m8n8.x4.shared.b16 {%0,%1,%2,%3}, [%4];"
        : "=r"(r[0]), "=r"(r[1]), "=r"(r[2]), "=r"(r[3]) : "r"(a));
}

__device__ __forceinline__ void mma16816(float* d, const uint32_t* a,
                                         uint32_t b0, uint32_t b1) {
    asm volatile(
        "mma.sync.aligned.m16n8k16.row.col.f32.bf16.bf16.f32 "
        "{%0,%1,%2,%3}, {%4,%5,%6,%7}, {%8,%9}, {%0,%1,%2,%3};"
        : "+f"(d[0]), "+f"(d[1]), "+f"(d[2]), "+f"(d[3])
        : "r"(a[0]), "r"(a[1]), "r"(a[2]), "r"(a[3]), "r"(b0), "r"(b1));
}

__device__ __forceinline__ float ex2f(float x) {
    float y;
    asm("ex2.approx.f32 %0, %1;" : "=f"(y) : "f"(x));
    return y;
}

__device__ __forceinline__ uint32_t pack2(float a, float b, float& ra, float& rb) {
    __nv_bfloat16 ah = __float2bfloat16_rn(a);
    __nv_bfloat16 bh = __float2bfloat16_rn(b);
    ra = a - __bfloat162float(ah);
    rb = b - __bfloat162float(bh);
    __nv_bfloat162 t = __halves2bfloat162(ah, bh);
    return *reinterpret_cast<uint32_t*>(&t);
}

__device__ __forceinline__ uint32_t pack2lo(float a, float b) {
    __nv_bfloat162 t = __halves2bfloat162(__float2bfloat16_rn(a),
                                          __float2bfloat16_rn(b));
    return *reinterpret_cast<uint32_t*>(&t);
}

#define CP16(d, s) \
    asm volatile("cp.async.cg.shared.global [%0], [%1], 16;" :: "r"(d), "l"(s))
#define CP_COMMIT() asm volatile("cp.async.commit_group;" ::: "memory")
#define CP_WAIT1()  asm volatile("cp.async.wait_group 1;" ::: "memory")
#define CP_WAIT0()  asm volatile("cp.async.wait_group 0;" ::: "memory")

// ---------------------------------------------------------------------------
// Shared GEMM mainloop: 3 stages x 4 tiles (Ah,Al,Bh,Bl) x 8KB = 96KB
// ---------------------------------------------------------------------------
#define TILE_B   8192
#define STAGE_B  (4 * TILE_B)
#define NSTAGES  3
#define MMA_SMEM (NSTAGES * STAGE_B)

__device__ __forceinline__ void cp_tile(uint32_t sdst, const __nv_bfloat16* g,
                                        int rs, int tid) {
    #pragma unroll
    for (int t = 0; t < 2; t++) {
        int u = tid + t * 256;
        int row = u >> 2, q = u & 3;
        uint32_t d = sdst + SMEM_SWIZZLE_64B((uint32_t)(row * 64 + q * 16));
        CP16(d, g + (size_t)row * rs + q * 8);
    }
}

__device__ __forceinline__ void mma_mainloop(
    uint32_t sbase,
    const __nv_bfloat16* Ah, const __nv_bfloat16* Al,
    const __nv_bfloat16* Bh, const __nv_bfloat16* Bl,
    int rsA, int rsB, int nch,
    float acc[4][4][4], int tid, int wid, int lane)
{
    const int iBase = (wid >> 2) * 64;
    const int jBase = (wid & 3) * 32;
    const uint32_t lsw  = (uint32_t)(((lane >> 1) & 3) * 16);
    const uint32_t aoff = (uint32_t)((iBase + (lane & 15)) * 64 + (lane >> 4) * 16);
    const uint32_t boff = (uint32_t)((jBase + (lane & 15)) * 64 + (lane >> 4) * 16);

    #pragma unroll
    for (int p = 0; p < 2; p++) {
        uint32_t st = sbase + p * STAGE_B;
        int ko = p * 32;
        cp_tile(st + 0 * TILE_B, Ah + ko, rsA, tid);
        cp_tile(st + 1 * TILE_B, Al + ko, rsA, tid);
        cp_tile(st + 2 * TILE_B, Bh + ko, rsB, tid);
        cp_tile(st + 3 * TILE_B, Bl + ko, rsB, tid);
        CP_COMMIT();
    }

    int stage = 0;
    #pragma unroll 1
    for (int c = 0; c < nch; c++) {
        if (c + 1 < nch) CP_WAIT1(); else CP_WAIT0();
        __syncthreads();

        if (c + 2 < nch) {
            int ps = stage + 2; if (ps >= NSTAGES) ps -= NSTAGES;
            uint32_t st = sbase + ps * STAGE_B;
            int ko = (c + 2) * 32;
            cp_tile(st + 0 * TILE_B, Ah + ko, rsA, tid);
            cp_tile(st + 1 * TILE_B, Al + ko, rsA, tid);
            cp_tile(st + 2 * TILE_B, Bh + ko, rsB, tid);
            cp_tile(st + 3 * TILE_B, Bl + ko, rsB, tid);
            CP_COMMIT();
        }

        uint32_t tb = sbase + stage * STAGE_B;
        #pragma unroll
        for (int ks = 0; ks < 2; ks++) {
            uint32_t kb = (uint32_t)(ks * 32);
            uint32_t ah[4][4], al[4][4];
            #pragma unroll
            for (int it = 0; it < 4; it++) {
                uint32_t o = (aoff + it * 1024 + kb) ^ lsw;
                ldmx4(ah[it], tb + o);
                ldmx4(al[it], tb + TILE_B + o);
            }
            uint32_t bh[4][2], bl[4][2];
            #pragma unroll
            for (int jp = 0; jp < 2; jp++) {
                uint32_t o = (boff + jp * 1024 + kb) ^ lsw;
                uint32_t t4[4];
                ldmx4(t4, tb + 2 * TILE_B + o);
                bh[jp * 2][0]     = t4[0]; bh[jp * 2][1]     = t4[2];
                bh[jp * 2 + 1][0] = t4[1]; bh[jp * 2 + 1][1] = t4[3];
                ldmx4(t4, tb + 3 * TILE_B + o);
                bl[jp * 2][0]     = t4[0]; bl[jp * 2][1]     = t4[2];
                bl[jp * 2 + 1][0] = t4[1]; bl[jp * 2 + 1][1] = t4[3];
            }
            #pragma unroll
            for (int it = 0; it < 4; it++)
                #pragma unroll
                for (int nt = 0; nt < 4; nt++)
                    mma16816(acc[it][nt], ah[it], bh[nt][0], bh[nt][1]);
            #pragma unroll
            for (int it = 0; it < 4; it++)
                #pragma unroll
                for (int nt = 0; nt < 4; nt++)
                    mma16816(acc[it][nt], ah[it], bl[nt][0], bl[nt][1]);
            #pragma unroll
            for (int it = 0; it < 4; it++)
                #pragma unroll
                for (int nt = 0; nt < 4; nt++)
                    mma16816(acc[it][nt], al[it], bh[nt][0], bh[nt][1]);
        }
        if (++stage == NSTAGES) stage = 0;
    }
}

// ---------------------------------------------------------------------------
// Kernel A: transpose + bf16 hi/lo split.  x [B,C,N] fp32 -> out [B,N,C].
// ---------------------------------------------------------------------------
__global__ void __launch_bounds__(256)
conv_split(const float* __restrict__ x,
           __nv_bfloat16* __restrict__ oh,
           __nv_bfloat16* __restrict__ ol) {
    __shared__ float ts[32][33];
    const int b = blockIdx.z, c0 = blockIdx.y * 32, n0 = blockIdx.x * 32;
    const int r = threadIdx.x >> 5, col = threadIdx.x & 31;

    const float* xb = x + ((size_t)b * Cn + c0) * Nn + n0;
    #pragma unroll
    for (int p = 0; p < 4; p++)
        ts[r + p * 8][col] = xb[(size_t)(r + p * 8) * Nn + col];
    __syncthreads();

    __nv_bfloat16* dh = oh + ((size_t)b * Nn + n0) * Cn + c0;
    __nv_bfloat16* dl = ol + ((size_t)b * Nn + n0) * Cn + c0;
    #pragma unroll
    for (int p = 0; p < 4; p++) {
        int n = r + p * 8;
        float f = ts[col][n];
        __nv_bfloat16 h = __float2bfloat16_rn(f);
        dh[(size_t)n * Cn + col] = h;
        dl[(size_t)n * Cn + col] = __float2bfloat16_rn(f - __bfloat162float(h));
    }
}

// ---------------------------------------------------------------------------
// Kernel B: split Wv (256 blocks) + zero Z (128 blocks) + zero bias (1 block).
// ---------------------------------------------------------------------------
__global__ void __launch_bounds__(256)
wsplit_zero(const float* __restrict__ Wv) {
    int bid = blockIdx.x;
    if (bid < 256) {
        int idx = bid * 256 + threadIdx.x;
        float f = Wv[idx];
        __nv_bfloat16 h = __float2bfloat16_rn(f);
        g_wvh[idx] = h;
        g_wvl[idx] = __float2bfloat16_rn(f - __bfloat162float(h));
    } else if (bid < 384) {
        g_Z[(size_t)(bid - 256) * 256 + threadIdx.x] = 0.f;
    } else {
        g_bzero[threadIdx.x] = 0.f;
    }
}

// ---------------------------------------------------------------------------
// Kernel B2: M = Wq^T Wk (rows 0..255), aw = Wk^T bq (256), bw = Wq^T bk (257),
// cc = bq.bk (258).
// ---------------------------------------------------------------------------
__global__ void __launch_bounds__(256)
mk_kernel(const float* __restrict__ Wq, const float* __restrict__ Wk,
          const float* __restrict__ bq, const float* __restrict__ bk) {
    const int bid = blockIdx.x, t = threadIdx.x;
    if (bid < 256) {
        const int c = bid;
        float acc = 0.f;
        #pragma unroll 4
        for (int o = 0; o < 256; o++)
            acc += Wq[o * 256 + c] * Wk[o * 256 + t];
        __nv_bfloat16 h = __float2bfloat16_rn(acc);
        g_Mh[c * 256 + t] = h;
        g_Ml[c * 256 + t] = __float2bfloat16_rn(acc - __bfloat162float(h));
    } else if (bid == 256) {
        float acc = 0.f;
        #pragma unroll 4
        for (int o = 0; o < 256; o++) acc += Wk[o * 256 + t] * bq[o];
        g_abw[t] = acc;
    } else if (bid == 257) {
        float acc = 0.f;
        #pragma unroll 4
        for (int o = 0; o < 256; o++) acc += Wq[o * 256 + t] * bk[o];
        g_abw[256 + t] = acc;
    } else {
        if (t < 32) {
            float s = 0.f;
            for (int o = t; o < 256; o += 32) s += bq[o] * bk[o];
            #pragma unroll
            for (int off = 16; off; off >>= 1)
                s += __shfl_xor_sync(0xffffffffu, s, off);
            if (t == 0) g_abw[512] = s;
        }
    }
}

// ---------------------------------------------------------------------------
// Kernel B3: alpha[b][j] = aw . xk[b][j] + cc ;  beta[b][i] = bw . xq[b][i]
// grid (512, Bn, 2), 8 warps/block, one row per warp.
// ---------------------------------------------------------------------------
__global__ void __launch_bounds__(256)
ab_kernel() {
    const int warp = threadIdx.x >> 5, lane = threadIdx.x & 31;
    const int b = blockIdx.y, which = blockIdx.z;
    const int j = blockIdx.x * 8 + warp;

    const __nv_bfloat16* xh = (which == 0 ? g_xkh : g_xqh) + ((size_t)b * Nn + j) * Cn;
    const __nv_bfloat16* xl = (which == 0 ? g_xkl : g_xql) + ((size_t)b * Nn + j) * Cn;
    const float* w = g_abw + which * 256;

    float s = 0.f;
    #pragma unroll
    for (int k = 0; k < 8; k++) {
        int d = lane + k * 32;
        float xv = __bfloat162float(xh[d]) + __bfloat162float(xl[d]);
        s += xv * w[d];
    }
    #pragma unroll
    for (int off = 16; off; off >>= 1)
        s += __shfl_xor_sync(0xffffffffu, s, off);
    if (lane == 0) {
        if (which == 0) g_alpha[(size_t)b * Nn + j] = s + g_abw[512];
        else            g_beta [(size_t)b * Nn + j] = s;
    }
}

// ---------------------------------------------------------------------------
// Kernel C1: GEMM -> [N, C]: out[n,o] = sum_c x[n,c]*W[o,c] + bias[o]
// Used for y = M xk (bias = 0).
// ---------------------------------------------------------------------------
__global__ void __launch_bounds__(256, 2)
proj_nk(const __nv_bfloat16* __restrict__ xh, const __nv_bfloat16* __restrict__ xl,
        const __nv_bfloat16* __restrict__ wh, const __nv_bfloat16* __restrict__ wl,
        const float* __restrict__ bias,
        __nv_bfloat16* __restrict__ oh, __nv_bfloat16* __restrict__ ol) {
    extern __shared__ char smem[];
    uint32_t sbase = smem_u32(smem);
    const int tid = threadIdx.x;
    const int wid = tid >> 5, lane = tid & 31;

    const int b  = blockIdx.z;
    const int n0 = blockIdx.y * 128;
    const int o0 = blockIdx.x * 128;

    float acc[4][4][4] = {};
    mma_mainloop(sbase,
                 xh + ((size_t)b * Nn + n0) * Cn, xl + ((size_t)b * Nn + n0) * Cn,
                 wh + (size_t)o0 * Cn,            wl + (size_t)o0 * Cn,
                 Cn, Cn, Cn / 32, acc, tid, wid, lane);

    const int iBase = (wid >> 2) * 64;
    const int jBase = (wid & 3) * 32;
    const int g = lane >> 2, cp2 = (lane & 3) * 2;
    __nv_bfloat16* dh = oh + (size_t)b * Nn * Cn;
    __nv_bfloat16* dl = ol + (size_t)b * Nn * Cn;

    #pragma unroll
    for (int nt = 0; nt < 4; nt++) {
        int cc = o0 + jBase + nt * 8 + cp2;
        float b0 = bias[cc], b1 = bias[cc + 1];
        #pragma unroll
        for (int it = 0; it < 4; it++) {
            int r1 = n0 + iBase + it * 16 + g;
            float l0, l1;
            uint32_t h01 = pack2(acc[it][nt][0] + b0, acc[it][nt][1] + b1, l0, l1);
            *reinterpret_cast<uint32_t*>(&dh[(size_t)r1 * Cn + cc]) = h01;
            *reinterpret_cast<uint32_t*>(&dl[(size_t)r1 * Cn + cc]) = pack2lo(l0, l1);
            uint32_t h23 = pack2(acc[it][nt][2] + b0, acc[it][nt][3] + b1, l0, l1);
            *reinterpret_cast<uint32_t*>(&dh[(size_t)(r1 + 8) * Cn + cc]) = h23;
            *reinterpret_cast<uint32_t*>(&dl[(size_t)(r1 + 8) * Cn + cc]) = pack2lo(l0, l1);
        }
    }
}

// ---------------------------------------------------------------------------
// Kernel C2: GEMM -> [C, N] (v).  out[o,n] = sum_c W[o,c]*x[n,c] + bias[o]
// ---------------------------------------------------------------------------
__global__ void __launch_bounds__(256, 2)
proj_cn(const __nv_bfloat16* __restrict__ wh, const __nv_bfloat16* __restrict__ wl,
        const __nv_bfloat16* __restrict__ xh, const __nv_bfloat16* __restrict__ xl,
        const float* __restrict__ bias,
        __nv_bfloat16* __restrict__ oh, __nv_bfloat16* __restrict__ ol) {
    extern __shared__ char smem[];
    uint32_t sbase = smem_u32(smem);
    const int tid = threadIdx.x;
    const int wid = tid >> 5, lane = tid & 31;

    const int b  = blockIdx.z;
    const int o0 = blockIdx.y * 128;
    const int n0 = blockIdx.x * 128;

    float acc[4][4][4] = {};
    mma_mainloop(sbase,
                 wh + (size_t)o0 * Cn,            wl + (size_t)o0 * Cn,
                 xh + ((size_t)b * Nn + n0) * Cn, xl + ((size_t)b * Nn + n0) * Cn,
                 Cn, Cn, Cn / 32, acc, tid, wid, lane);

    const int iBase = (wid >> 2) * 64;
    const int jBase = (wid & 3) * 32;
    const int g = lane >> 2, cp2 = (lane & 3) * 2;
    __nv_bfloat16* dh = oh + (size_t)b * Cn * Nn;
    __nv_bfloat16* dl = ol + (size_t)b * Cn * Nn;

    #pragma unroll
    for (int it = 0; it < 4; it++) {
        int r1 = o0 + iBase + it * 16 + g;
        float br1 = bias[r1], br2 = bias[r1 + 8];
        #pragma unroll
        for (int nt = 0; nt < 4; nt++) {
            int cc = n0 + jBase + nt * 8 + cp2;
            float l0, l1;
            uint32_t h01 = pack2(acc[it][nt][0] + br1, acc[it][nt][1] + br1, l0, l1);
            *reinterpret_cast<uint32_t*>(&dh[(size_t)r1 * Nn + cc]) = h01;
            *reinterpret_cast<uint32_t*>(&dl[(size_t)r1 * Nn + cc]) = pack2lo(l0, l1);
            uint32_t h23 = pack2(acc[it][nt][2] + br2, acc[it][nt][3] + br2, l0, l1);
            *reinterpret_cast<uint32_t*>(&dh[(size_t)(r1 + 8) * Nn + cc]) = h23;
            *reinterpret_cast<uint32_t*>(&dl[(size_t)(r1 + 8) * Nn + cc]) = pack2lo(l0, l1);
        }
    }
}

// ---------------------------------------------------------------------------
// Kernel D: scores = xq . y + beta_i + alpha_j, masked; store E + Z sums.
// ---------------------------------------------------------------------------
__global__ void __launch_bounds__(256, 2)
scores_mma(const float* __restrict__ mask) {
    extern __shared__ char smem[];
    uint32_t sbase = smem_u32(smem);
    const int tid = threadIdx.x;
    const int wid = tid >> 5, lane = tid & 31;

    const int b  = blockIdx.z;
    const int i0 = blockIdx.y * 128;
    const int j0 = blockIdx.x * 128;

    float acc[4][4][4] = {};
    mma_mainloop(sbase,
                 g_xqh + ((size_t)b * Nn + i0) * Cn, g_xql + ((size_t)b * Nn + i0) * Cn,
                 g_yh  + ((size_t)b * Nn + j0) * Cn, g_yl  + ((size_t)b * Nn + j0) * Cn,
                 Cn, Cn, Cn / 32, acc, tid, wid, lane);

    const int iBase = (wid >> 2) * 64;
    const int jBase = (wid & 3) * 32;
    const int g = lane >> 2, cp2 = (lane & 3) * 2;
    const float* mb = mask + (size_t)b * Nn;
    const float* Ab = g_alpha + (size_t)b * Nn;
    const float* Bt = g_beta  + (size_t)b * Nn;
    __nv_bfloat16* Ehb = g_Eh + (size_t)b * Nn * Nn;
    __nv_bfloat16* Elb = g_El + (size_t)b * Nn * Nn;
    float* Zb = g_Z + (size_t)b * Nn;

    float a0[4], a1[4];
    #pragma unroll
    for (int nt = 0; nt < 4; nt++) {
        int cc = j0 + jBase + nt * 8 + cp2;
        a0[nt] = Ab[cc];
        a1[nt] = Ab[cc + 1];
    }

    #pragma unroll
    for (int it = 0; it < 4; it++) {
        int r1 = i0 + iBase + it * 16 + g;
        float m1 = mb[r1], m2 = mb[r1 + 8];
        float bi1 = Bt[r1], bi2 = Bt[r1 + 8];
        float z1 = 0.f, z2 = 0.f;
        #pragma unroll
        for (int nt = 0; nt < 4; nt++) {
            int cc = j0 + jBase + nt * 8 + cp2;
            float e0 = ex2f(fmaf((acc[it][nt][0] + bi1 + a0[nt]) * m1, L2E, -C2));
            float e1 = ex2f(fmaf((acc[it][nt][1] + bi1 + a1[nt]) * m1, L2E, -C2));
            float e2 = ex2f(fmaf((acc[it][nt][2] + bi2 + a0[nt]) * m2, L2E, -C2));
            float e3 = ex2f(fmaf((acc[it][nt][3] + bi2 + a1[nt]) * m2, L2E, -C2));
            z1 += e0 + e1;
            z2 += e2 + e3;
            float l0, l1;
            uint32_t h01 = pack2(e0, e1, l0, l1);
            *reinterpret_cast<uint32_t*>(&Ehb[(size_t)r1 * Nn + cc]) = h01;
            *reinterpret_cast<uint32_t*>(&Elb[(size_t)r1 * Nn + cc]) = pack2lo(l0, l1);
            uint32_t h23 = pack2(e2, e3, l0, l1);
            *reinterpret_cast<uint32_t*>(&Ehb[(size_t)(r1 + 8) * Nn + cc]) = h23;
            *reinterpret_cast<uint32_t*>(&Elb[(size_t)(r1 + 8) * Nn + cc]) = pack2lo(l0, l1);
        }
        z1 += __shfl_xor_sync(0xffffffffu, z1, 1);
        z1 += __shfl_xor_sync(0xffffffffu, z1, 2);
        z2 += __shfl_xor_sync(0xffffffffu, z2, 1);
        z2 += __shfl_xor_sync(0xffffffffu, z2, 2);
        if ((lane & 3) == 0) {
            atomicAdd(&Zb[r1], z1);
            atomicAdd(&Zb[r1 + 8], z2);
        }
    }
}

// ---------------------------------------------------------------------------
// Kernel E: PV GEMM on unnormalized E + normalize/blend epilogue.
// ---------------------------------------------------------------------------
__global__ void __launch_bounds__(256, 2)
pv_mma(const float* __restrict__ mask,
       const float* __restrict__ queries,
       float* __restrict__ out) {
    extern __shared__ char smem[];
    uint32_t sbase = smem_u32(smem);
    const int tid = threadIdx.x;
    const int wid = tid >> 5, lane = tid & 31;

    const int b  = blockIdx.z;
    const int c0 = blockIdx.y * 128;
    const int q0 = blockIdx.x * 128;

    float acc[4][4][4] = {};
    mma_mainloop(sbase,
                 g_vh + ((size_t)b * Cn + c0) * Nn, g_vl + ((size_t)b * Cn + c0) * Nn,
                 g_Eh + ((size_t)b * Nn + q0) * Nn, g_El + ((size_t)b * Nn + q0) * Nn,
                 Nn, Nn, Nn / 32, acc, tid, wid, lane);

    const int iBase = (wid >> 2) * 64;
    const int jBase = (wid & 3) * 32;
    const int g = lane >> 2, cp2 = (lane & 3) * 2;
    const float* mb = mask + (size_t)b * Nn;
    const float* Zb = g_Z + (size_t)b * Nn;

    int   qc[4];
    float m0[4], m1[4], iz0[4], iz1[4];
    #pragma unroll
    for (int nt = 0; nt < 4; nt++) {
        qc[nt] = q0 + jBase + nt * 8 + cp2;
        m0[nt] = mb[qc[nt]];
        m1[nt] = mb[qc[nt] + 1];
        iz0[nt] = __fdividef(1.f, Zb[qc[nt]]);
        iz1[nt] = __fdividef(1.f, Zb[qc[nt] + 1]);
    }

    #pragma unroll
    for (int it = 0; it < 4; it++) {
        int cr = c0 + iBase + it * 16 + g;
        #pragma unroll
        for (int nt = 0; nt < 4; nt++) {
            size_t gi1 = ((size_t)b * Cn + cr) * Nn + qc[nt];
            size_t gi2 = gi1 + (size_t)8 * Nn;
            float2 qa = *reinterpret_cast<const float2*>(&queries[gi1]);
            float2 qb = *reinterpret_cast<const float2*>(&queries[gi2]);
            float2 o1, o2;
            o1.x = qa.x * m0[nt] + (1.f - m0[nt]) * acc[it][nt][0] * iz0[nt];
            o1.y = qa.y * m1[nt] + (1.f - m1[nt]) * acc[it][nt][1] * iz1[nt];
            o2.x = qb.x * m0[nt] + (1.f - m0[nt]) * acc[it][nt][2] * iz0[nt];
            o2.y = qb.y * m1[nt] + (1.f - m1[nt]) * acc[it][nt][3] * iz1[nt];
            *reinterpret_cast<float2*>(&out[gi1]) = o1;
            *reinterpret_cast<float2*>(&out[gi2]) = o2;
        }
    }
}

// ---------------------------------------------------------------------------
// Launch
// ---------------------------------------------------------------------------
extern "C" void kernel_launch(void* const* d_in, const int* in_sizes, int n_in,
                              void* d_out, int out_size) {
    const float* queries = (const float*)d_in[0];
    const float* keys    = (const float*)d_in[1];
    const float* mask    = (const float*)d_in[2];
    const float* Wq      = (const float*)d_in[3];
    const float* bq      = (const float*)d_in[4];
    const float* Wk      = (const float*)d_in[5];
    const float* bk      = (const float*)d_in[6];
    const float* Wv      = (const float*)d_in[7];
    const float* bv      = (const float*)d_in[8];
    float* out = (float*)d_out;

    cudaFuncSetAttribute(proj_nk,    cudaFuncAttributeMaxDynamicSharedMemorySize, MMA_SMEM);
    cudaFuncSetAttribute(proj_cn,    cudaFuncAttributeMaxDynamicSharedMemorySize, MMA_SMEM);
    cudaFuncSetAttribute(scores_mma, cudaFuncAttributeMaxDynamicSharedMemorySize, MMA_SMEM);
    cudaFuncSetAttribute(pv_mma,     cudaFuncAttributeMaxDynamicSharedMemorySize, MMA_SMEM);

    __nv_bfloat16 *xqh, *xql, *xkh, *xkl, *Mh, *Ml, *wvh, *wvl, *yh, *yl, *vh, *vl;
    float* bz;
    cudaGetSymbolAddress((void**)&xqh, g_xqh);
    cudaGetSymbolAddress((void**)&xql, g_xql);
    cudaGetSymbolAddress((void**)&xkh, g_xkh);
    cudaGetSymbolAddress((void**)&xkl, g_xkl);
    cudaGetSymbolAddress((void**)&Mh,  g_Mh);
    cudaGetSymbolAddress((void**)&Ml,  g_Ml);
    cudaGetSymbolAddress((void**)&wvh, g_wvh);
    cudaGetSymbolAddress((void**)&wvl, g_wvl);
    cudaGetSymbolAddress((void**)&yh,  g_yh);
    cudaGetSymbolAddress((void**)&yl,  g_yl);
    cudaGetSymbolAddress((void**)&vh,  g_vh);
    cudaGetSymbolAddress((void**)&vl,  g_vl);
    cudaGetSymbolAddress((void**)&bz,  g_bzero);

    // Input transpose + split
    dim3 gcv(Nn / 32, Cn / 32, Bn);
    conv_split<<<gcv, 256>>>(queries, xqh, xql);
    conv_split<<<gcv, 256>>>(keys,    xkh, xkl);
    wsplit_zero<<<385, 256>>>(Wv);
    mk_kernel<<<259, 256>>>(Wq, Wk, bq, bk);
    dim3 gab(Nn / 8, Bn, 2);
    ab_kernel<<<gab, 256>>>();

    // y = M xk (replaces q and k projections); v projection
    dim3 gnk(Cn / 128, Nn / 128, Bn);
    proj_nk<<<gnk, 256, MMA_SMEM>>>(xkh, xkl, Mh, Ml, bz, yh, yl);
    dim3 gcn(Nn / 128, Cn / 128, Bn);
    proj_cn<<<gcn, 256, MMA_SMEM>>>(wvh, wvl, xkh, xkl, bv, vh, vl);

    // Scores -> E (unnormalized exp) + Z
    dim3 gsc(Nn / 128, Nn / 128, Bn);
    scores_mma<<<gsc, 256, MMA_SMEM>>>(mask);

    // PV + normalize + blend
    dim3 gpv(Nn / 128, Cn / 128, Bn);
    pv_mma<<<gpv, 256, MMA_SMEM>>>(mask, queries, out);
}

// round 14
// speedup vs baseline: 1.0503x; 1.0103x over previous
#include <cuda_runtime.h>
#include <cuda_bf16.h>
#include <cstdint>
#include <math.h>

#define Bn 8
#define Cn 256
#define Nn 4096

#define L2E 1.4426950408889634f
#define C2  72.134752f        // 50 * log2(e)

// ---------------------------------------------------------------------------
// Scratch
// ---------------------------------------------------------------------------
__device__ __nv_bfloat16 g_xqh[(size_t)Bn * Nn * Cn];  // queries^T hi [B,N,C]
__device__ __nv_bfloat16 g_xql[(size_t)Bn * Nn * Cn];
__device__ __nv_bfloat16 g_xkh[(size_t)Bn * Nn * Cn];  // keys^T hi [B,N,C]
__device__ __nv_bfloat16 g_xkl[(size_t)Bn * Nn * Cn];
__device__ __nv_bfloat16 g_Mh[Cn * Cn];                // M = Wq^T Wk  [c][d]
__device__ __nv_bfloat16 g_Ml[Cn * Cn];
__device__ __nv_bfloat16 g_wvh[Cn * Cn];               // Wv hi [O,C]
__device__ __nv_bfloat16 g_wvl[Cn * Cn];
__device__ __nv_bfloat16 g_yh[(size_t)Bn * Nn * Cn];   // y = M xk  [B,N,C]
__device__ __nv_bfloat16 g_yl[(size_t)Bn * Nn * Cn];
__device__ __nv_bfloat16 g_vh[(size_t)Bn * Cn * Nn];   // v hi [B,C,N]
__device__ __nv_bfloat16 g_vl[(size_t)Bn * Cn * Nn];
__device__ __nv_bfloat16 g_Eh[(size_t)Bn * Nn * Nn];   // exp(s-50) hi [B,N,N]
__device__ __nv_bfloat16 g_El[(size_t)Bn * Nn * Nn];
__device__ float         g_Z [(size_t)Bn * Nn];        // row exp sums
__device__ float         g_abw[513];                   // aw[256] | bw[256] | cc
__device__ float         g_alpha[(size_t)Bn * Nn];     // per-j bias (init cc)
__device__ float         g_beta [(size_t)Bn * Nn];     // per-i bias (init 0)
__device__ float         g_bzero[Cn];                  // zero bias

// ---------------------------------------------------------------------------
// Helpers
// ---------------------------------------------------------------------------
__device__ __forceinline__ uint32_t smem_u32(const void* p) {
    uint32_t a;
    asm("{ .reg .u64 t; cvta.to.shared.u64 t, %1; cvt.u32.u64 %0, t; }"
        : "=r"(a) : "l"(p));
    return a;
}

#define SMEM_SWIZZLE_64B(off) ((off) ^ (((off) >> 3) & 0x30))

__device__ __forceinline__ void ldmx4(uint32_t* r, uint32_t a) {
    asm volatile("ldmatrix.sync.aligned.m8n8.x4.shared.b16 {%0,%1,%2,%3}, [%4];"
        : "=r"(r[0]), "=r"(r[1]), "=r"(r[2]), "=r"(r[3]) : "r"(a));
}

__device__ __forceinline__ void mma16816(float* d, const uint32_t* a,
                                         uint32_t b0, uint32_t b1) {
    asm volatile(
        "mma.sync.aligned.m16n8k16.row.col.f32.bf16.bf16.f32 "
        "{%0,%1,%2,%3}, {%4,%5,%6,%7}, {%8,%9}, {%0,%1,%2,%3};"
        : "+f"(d[0]), "+f"(d[1]), "+f"(d[2]), "+f"(d[3])
        : "r"(a[0]), "r"(a[1]), "r"(a[2]), "r"(a[3]), "r"(b0), "r"(b1));
}

__device__ __forceinline__ float ex2f(float x) {
    float y;
    asm("ex2.approx.f32 %0, %1;" : "=f"(y) : "f"(x));
    return y;
}

__device__ __forceinline__ uint32_t pack2(float a, float b, float& ra, float& rb) {
    __nv_bfloat16 ah = __float2bfloat16_rn(a);
    __nv_bfloat16 bh = __float2bfloat16_rn(b);
    ra = a - __bfloat162float(ah);
    rb = b - __bfloat162float(bh);
    __nv_bfloat162 t = __halves2bfloat162(ah, bh);
    return *reinterpret_cast<uint32_t*>(&t);
}

__device__ __forceinline__ uint32_t pack2lo(float a, float b) {
    __nv_bfloat162 t = __halves2bfloat162(__float2bfloat16_rn(a),
                                          __float2bfloat16_rn(b));
    return *reinterpret_cast<uint32_t*>(&t);
}

#define CP16(d, s) \
    asm volatile("cp.async.cg.shared.global [%0], [%1], 16;" :: "r"(d), "l"(s))
#define CP_COMMIT() asm volatile("cp.async.commit_group;" ::: "memory")
#define CP_WAIT1()  asm volatile("cp.async.wait_group 1;" ::: "memory")
#define CP_WAIT0()  asm volatile("cp.async.wait_group 0;" ::: "memory")

// ---------------------------------------------------------------------------
// Shared GEMM mainloop: 3 stages x 4 tiles (Ah,Al,Bh,Bl) x 8KB = 96KB
// ---------------------------------------------------------------------------
#define TILE_B   8192
#define STAGE_B  (4 * TILE_B)
#define NSTAGES  3
#define MMA_SMEM (NSTAGES * STAGE_B)

__device__ __forceinline__ void cp_tile(uint32_t sdst, const __nv_bfloat16* g,
                                        int rs, int tid) {
    #pragma unroll
    for (int t = 0; t < 2; t++) {
        int u = tid + t * 256;
        int row = u >> 2, q = u & 3;
        uint32_t d = sdst + SMEM_SWIZZLE_64B((uint32_t)(row * 64 + q * 16));
        CP16(d, g + (size_t)row * rs + q * 8);
    }
}

__device__ __forceinline__ void mma_mainloop(
    uint32_t sbase,
    const __nv_bfloat16* Ah, const __nv_bfloat16* Al,
    const __nv_bfloat16* Bh, const __nv_bfloat16* Bl,
    int rsA, int rsB, int nch,
    float acc[4][4][4], int tid, int wid, int lane)
{
    const int iBase = (wid >> 2) * 64;
    const int jBase = (wid & 3) * 32;
    const uint32_t lsw  = (uint32_t)(((lane >> 1) & 3) * 16);
    const uint32_t aoff = (uint32_t)((iBase + (lane & 15)) * 64 + (lane >> 4) * 16);
    const uint32_t boff = (uint32_t)((jBase + (lane & 15)) * 64 + (lane >> 4) * 16);

    #pragma unroll
    for (int p = 0; p < 2; p++) {
        uint32_t st = sbase + p * STAGE_B;
        int ko = p * 32;
        cp_tile(st + 0 * TILE_B, Ah + ko, rsA, tid);
        cp_tile(st + 1 * TILE_B, Al + ko, rsA, tid);
        cp_tile(st + 2 * TILE_B, Bh + ko, rsB, tid);
        cp_tile(st + 3 * TILE_B, Bl + ko, rsB, tid);
        CP_COMMIT();
    }

    int stage = 0;
    #pragma unroll 1
    for (int c = 0; c < nch; c++) {
        if (c + 1 < nch) CP_WAIT1(); else CP_WAIT0();
        __syncthreads();

        if (c + 2 < nch) {
            int ps = stage + 2; if (ps >= NSTAGES) ps -= NSTAGES;
            uint32_t st = sbase + ps * STAGE_B;
            int ko = (c + 2) * 32;
            cp_tile(st + 0 * TILE_B, Ah + ko, rsA, tid);
            cp_tile(st + 1 * TILE_B, Al + ko, rsA, tid);
            cp_tile(st + 2 * TILE_B, Bh + ko, rsB, tid);
            cp_tile(st + 3 * TILE_B, Bl + ko, rsB, tid);
            CP_COMMIT();
        }

        uint32_t tb = sbase + stage * STAGE_B;
        #pragma unroll
        for (int ks = 0; ks < 2; ks++) {
            uint32_t kb = (uint32_t)(ks * 32);
            uint32_t ah[4][4], al[4][4];
            #pragma unroll
            for (int it = 0; it < 4; it++) {
                uint32_t o = (aoff + it * 1024 + kb) ^ lsw;
                ldmx4(ah[it], tb + o);
                ldmx4(al[it], tb + TILE_B + o);
            }
            uint32_t bh[4][2], bl[4][2];
            #pragma unroll
            for (int jp = 0; jp < 2; jp++) {
                uint32_t o = (boff + jp * 1024 + kb) ^ lsw;
                uint32_t t4[4];
                ldmx4(t4, tb + 2 * TILE_B + o);
                bh[jp * 2][0]     = t4[0]; bh[jp * 2][1]     = t4[2];
                bh[jp * 2 + 1][0] = t4[1]; bh[jp * 2 + 1][1] = t4[3];
                ldmx4(t4, tb + 3 * TILE_B + o);
                bl[jp * 2][0]     = t4[0]; bl[jp * 2][1]     = t4[2];
                bl[jp * 2 + 1][0] = t4[1]; bl[jp * 2 + 1][1] = t4[3];
            }
            #pragma unroll
            for (int it = 0; it < 4; it++)
                #pragma unroll
                for (int nt = 0; nt < 4; nt++)
                    mma16816(acc[it][nt], ah[it], bh[nt][0], bh[nt][1]);
            #pragma unroll
            for (int it = 0; it < 4; it++)
                #pragma unroll
                for (int nt = 0; nt < 4; nt++)
                    mma16816(acc[it][nt], ah[it], bl[nt][0], bl[nt][1]);
            #pragma unroll
            for (int it = 0; it < 4; it++)
                #pragma unroll
                for (int nt = 0; nt < 4; nt++)
                    mma16816(acc[it][nt], al[it], bh[nt][0], bh[nt][1]);
        }
        if (++stage == NSTAGES) stage = 0;
    }
}

// ---------------------------------------------------------------------------
// Kernel B2: M = Wq^T Wk (4-way ILP), aw = Wk^T bq, bw = Wq^T bk, cc = bq.bk.
// Runs FIRST (depends only on weights).
// ---------------------------------------------------------------------------
__global__ void __launch_bounds__(256)
mk_kernel(const float* __restrict__ Wq, const float* __restrict__ Wk,
          const float* __restrict__ bq, const float* __restrict__ bk) {
    const int bid = blockIdx.x, t = threadIdx.x;
    if (bid < 256) {
        const int c = bid;
        float a0 = 0.f, a1 = 0.f, a2 = 0.f, a3 = 0.f;
        #pragma unroll 4
        for (int o = 0; o < 256; o += 4) {
            a0 += Wq[(o + 0) * 256 + c] * Wk[(o + 0) * 256 + t];
            a1 += Wq[(o + 1) * 256 + c] * Wk[(o + 1) * 256 + t];
            a2 += Wq[(o + 2) * 256 + c] * Wk[(o + 2) * 256 + t];
            a3 += Wq[(o + 3) * 256 + c] * Wk[(o + 3) * 256 + t];
        }
        float acc = (a0 + a1) + (a2 + a3);
        __nv_bfloat16 h = __float2bfloat16_rn(acc);
        g_Mh[c * 256 + t] = h;
        g_Ml[c * 256 + t] = __float2bfloat16_rn(acc - __bfloat162float(h));
    } else if (bid == 256) {
        float a0 = 0.f, a1 = 0.f;
        #pragma unroll 4
        for (int o = 0; o < 256; o += 2) {
            a0 += Wk[(o + 0) * 256 + t] * bq[o + 0];
            a1 += Wk[(o + 1) * 256 + t] * bq[o + 1];
        }
        g_abw[t] = a0 + a1;
    } else if (bid == 257) {
        float a0 = 0.f, a1 = 0.f;
        #pragma unroll 4
        for (int o = 0; o < 256; o += 2) {
            a0 += Wq[(o + 0) * 256 + t] * bk[o + 0];
            a1 += Wq[(o + 1) * 256 + t] * bk[o + 1];
        }
        g_abw[256 + t] = a0 + a1;
    } else {
        if (t < 32) {
            float s = 0.f;
            for (int o = t; o < 256; o += 32) s += bq[o] * bk[o];
            #pragma unroll
            for (int off = 16; off; off >>= 1)
                s += __shfl_xor_sync(0xffffffffu, s, off);
            if (t == 0) g_abw[512] = s;
        }
    }
}

// ---------------------------------------------------------------------------
// Kernel B: split Wv + zero Z + zero bias + init alpha (=cc) / beta (=0).
// Runs after mk_kernel (reads g_abw[512]).
// blocks: [0,256) Wv | [256,384) Z | 384 bzero | [385,513) alpha | [513,641) beta
// ---------------------------------------------------------------------------
__global__ void __launch_bounds__(256)
wsplit_zero(const float* __restrict__ Wv) {
    int bid = blockIdx.x;
    if (bid < 256) {
        int idx = bid * 256 + threadIdx.x;
        float f = Wv[idx];
        __nv_bfloat16 h = __float2bfloat16_rn(f);
        g_wvh[idx] = h;
        g_wvl[idx] = __float2bfloat16_rn(f - __bfloat162float(h));
    } else if (bid < 384) {
        g_Z[(size_t)(bid - 256) * 256 + threadIdx.x] = 0.f;
    } else if (bid == 384) {
        g_bzero[threadIdx.x] = 0.f;
    } else if (bid < 513) {
        g_alpha[(size_t)(bid - 385) * 256 + threadIdx.x] = g_abw[512];
    } else {
        g_beta[(size_t)(bid - 513) * 256 + threadIdx.x] = 0.f;
    }
}

// ---------------------------------------------------------------------------
// Kernel A: transpose + bf16 hi/lo split + fused dot-product accumulation.
// x [B,C,N] fp32 -> out [B,N,C];  dotout[b][n] += sum_c x[c][n] * w[c].
// ---------------------------------------------------------------------------
__global__ void __launch_bounds__(256)
conv_split(const float* __restrict__ x,
           __nv_bfloat16* __restrict__ oh,
           __nv_bfloat16* __restrict__ ol,
           const float* __restrict__ w,
           float* __restrict__ dotout) {
    __shared__ float ts[32][33];
    const int b = blockIdx.z, c0 = blockIdx.y * 32, n0 = blockIdx.x * 32;
    const int r = threadIdx.x >> 5, col = threadIdx.x & 31;

    const float* xb = x + ((size_t)b * Cn + c0) * Nn + n0;
    #pragma unroll
    for (int p = 0; p < 4; p++)
        ts[r + p * 8][col] = xb[(size_t)(r + p * 8) * Nn + col];
    __syncthreads();

    __nv_bfloat16* dh = oh + ((size_t)b * Nn + n0) * Cn + c0;
    __nv_bfloat16* dl = ol + ((size_t)b * Nn + n0) * Cn + c0;
    #pragma unroll
    for (int p = 0; p < 4; p++) {
        int n = r + p * 8;
        float f = ts[col][n];
        __nv_bfloat16 h = __float2bfloat16_rn(f);
        dh[(size_t)n * Cn + col] = h;
        dl[(size_t)n * Cn + col] = __float2bfloat16_rn(f - __bfloat162float(h));
    }

    // Fused partial dot: warp r handles rows {r, r+8, r+16, r+24}; lane = c.
    const float wv = w[c0 + col];
    #pragma unroll
    for (int p = 0; p < 4; p++) {
        int n = r + p * 8;
        float s = ts[col][n] * wv;
        #pragma unroll
        for (int off = 16; off; off >>= 1)
            s += __shfl_xor_sync(0xffffffffu, s, off);
        if (col == 0)
            atomicAdd(&dotout[(size_t)b * Nn + n0 + n], s);
    }
}

// ---------------------------------------------------------------------------
// Kernel C1: GEMM -> [N, C]: out[n,o] = sum_c x[n,c]*W[o,c] + bias[o]
// ---------------------------------------------------------------------------
__global__ void __launch_bounds__(256, 2)
proj_nk(const __nv_bfloat16* __restrict__ xh, const __nv_bfloat16* __restrict__ xl,
        const __nv_bfloat16* __restrict__ wh, const __nv_bfloat16* __restrict__ wl,
        const float* __restrict__ bias,
        __nv_bfloat16* __restrict__ oh, __nv_bfloat16* __restrict__ ol) {
    extern __shared__ char smem[];
    uint32_t sbase = smem_u32(smem);
    const int tid = threadIdx.x;
    const int wid = tid >> 5, lane = tid & 31;

    const int b  = blockIdx.z;
    const int n0 = blockIdx.y * 128;
    const int o0 = blockIdx.x * 128;

    float acc[4][4][4] = {};
    mma_mainloop(sbase,
                 xh + ((size_t)b * Nn + n0) * Cn, xl + ((size_t)b * Nn + n0) * Cn,
                 wh + (size_t)o0 * Cn,            wl + (size_t)o0 * Cn,
                 Cn, Cn, Cn / 32, acc, tid, wid, lane);

    const int iBase = (wid >> 2) * 64;
    const int jBase = (wid & 3) * 32;
    const int g = lane >> 2, cp2 = (lane & 3) * 2;
    __nv_bfloat16* dh = oh + (size_t)b * Nn * Cn;
    __nv_bfloat16* dl = ol + (size_t)b * Nn * Cn;

    #pragma unroll
    for (int nt = 0; nt < 4; nt++) {
        int cc = o0 + jBase + nt * 8 + cp2;
        float b0 = bias[cc], b1 = bias[cc + 1];
        #pragma unroll
        for (int it = 0; it < 4; it++) {
            int r1 = n0 + iBase + it * 16 + g;
            float l0, l1;
            uint32_t h01 = pack2(acc[it][nt][0] + b0, acc[it][nt][1] + b1, l0, l1);
            *reinterpret_cast<uint32_t*>(&dh[(size_t)r1 * Cn + cc]) = h01;
            *reinterpret_cast<uint32_t*>(&dl[(size_t)r1 * Cn + cc]) = pack2lo(l0, l1);
            uint32_t h23 = pack2(acc[it][nt][2] + b0, acc[it][nt][3] + b1, l0, l1);
            *reinterpret_cast<uint32_t*>(&dh[(size_t)(r1 + 8) * Cn + cc]) = h23;
            *reinterpret_cast<uint32_t*>(&dl[(size_t)(r1 + 8) * Cn + cc]) = pack2lo(l0, l1);
        }
    }
}

// ---------------------------------------------------------------------------
// Kernel C2: GEMM -> [C, N] (v).  out[o,n] = sum_c W[o,c]*x[n,c] + bias[o]
// ---------------------------------------------------------------------------
__global__ void __launch_bounds__(256, 2)
proj_cn(const __nv_bfloat16* __restrict__ wh, const __nv_bfloat16* __restrict__ wl,
        const __nv_bfloat16* __restrict__ xh, const __nv_bfloat16* __restrict__ xl,
        const float* __restrict__ bias,
        __nv_bfloat16* __restrict__ oh, __nv_bfloat16* __restrict__ ol) {
    extern __shared__ char smem[];
    uint32_t sbase = smem_u32(smem);
    const int tid = threadIdx.x;
    const int wid = tid >> 5, lane = tid & 31;

    const int b  = blockIdx.z;
    const int o0 = blockIdx.y * 128;
    const int n0 = blockIdx.x * 128;

    float acc[4][4][4] = {};
    mma_mainloop(sbase,
                 wh + (size_t)o0 * Cn,            wl + (size_t)o0 * Cn,
                 xh + ((size_t)b * Nn + n0) * Cn, xl + ((size_t)b * Nn + n0) * Cn,
                 Cn, Cn, Cn / 32, acc, tid, wid, lane);

    const int iBase = (wid >> 2) * 64;
    const int jBase = (wid & 3) * 32;
    const int g = lane >> 2, cp2 = (lane & 3) * 2;
    __nv_bfloat16* dh = oh + (size_t)b * Cn * Nn;
    __nv_bfloat16* dl = ol + (size_t)b * Cn * Nn;

    #pragma unroll
    for (int it = 0; it < 4; it++) {
        int r1 = o0 + iBase + it * 16 + g;
        float br1 = bias[r1], br2 = bias[r1 + 8];
        #pragma unroll
        for (int nt = 0; nt < 4; nt++) {
            int cc = n0 + jBase + nt * 8 + cp2;
            float l0, l1;
            uint32_t h01 = pack2(acc[it][nt][0] + br1, acc[it][nt][1] + br1, l0, l1);
            *reinterpret_cast<uint32_t*>(&dh[(size_t)r1 * Nn + cc]) = h01;
            *reinterpret_cast<uint32_t*>(&dl[(size_t)r1 * Nn + cc]) = pack2lo(l0, l1);
            uint32_t h23 = pack2(acc[it][nt][2] + br2, acc[it][nt][3] + br2, l0, l1);
            *reinterpret_cast<uint32_t*>(&dh[(size_t)(r1 + 8) * Nn + cc]) = h23;
            *reinterpret_cast<uint32_t*>(&dl[(size_t)(r1 + 8) * Nn + cc]) = pack2lo(l0, l1);
        }
    }
}

// ---------------------------------------------------------------------------
// Kernel D: scores = xq . y + beta_i + alpha_j, masked; store E + Z sums.
// ---------------------------------------------------------------------------
__global__ void __launch_bounds__(256, 2)
scores_mma(const float* __restrict__ mask) {
    extern __shared__ char smem[];
    uint32_t sbase = smem_u32(smem);
    const int tid = threadIdx.x;
    const int wid = tid >> 5, lane = tid & 31;

    const int b  = blockIdx.z;
    const int i0 = blockIdx.y * 128;
    const int j0 = blockIdx.x * 128;

    float acc[4][4][4] = {};
    mma_mainloop(sbase,
                 g_xqh + ((size_t)b * Nn + i0) * Cn, g_xql + ((size_t)b * Nn + i0) * Cn,
                 g_yh  + ((size_t)b * Nn + j0) * Cn, g_yl  + ((size_t)b * Nn + j0) * Cn,
                 Cn, Cn, Cn / 32, acc, tid, wid, lane);

    const int iBase = (wid >> 2) * 64;
    const int jBase = (wid & 3) * 32;
    const int g = lane >> 2, cp2 = (lane & 3) * 2;
    const float* mb = mask + (size_t)b * Nn;
    const float* Ab = g_alpha + (size_t)b * Nn;
    const float* Bt = g_beta  + (size_t)b * Nn;
    __nv_bfloat16* Ehb = g_Eh + (size_t)b * Nn * Nn;
    __nv_bfloat16* Elb = g_El + (size_t)b * Nn * Nn;
    float* Zb = g_Z + (size_t)b * Nn;

    float a0[4], a1[4];
    #pragma unroll
    for (int nt = 0; nt < 4; nt++) {
        int cc = j0 + jBase + nt * 8 + cp2;
        a0[nt] = Ab[cc];
        a1[nt] = Ab[cc + 1];
    }

    #pragma unroll
    for (int it = 0; it < 4; it++) {
        int r1 = i0 + iBase + it * 16 + g;
        float m1 = mb[r1], m2 = mb[r1 + 8];
        float bi1 = Bt[r1], bi2 = Bt[r1 + 8];
        float z1 = 0.f, z2 = 0.f;
        #pragma unroll
        for (int nt = 0; nt < 4; nt++) {
            int cc = j0 + jBase + nt * 8 + cp2;
            float e0 = ex2f(fmaf((acc[it][nt][0] + bi1 + a0[nt]) * m1, L2E, -C2));
            float e1 = ex2f(fmaf((acc[it][nt][1] + bi1 + a1[nt]) * m1, L2E, -C2));
            float e2 = ex2f(fmaf((acc[it][nt][2] + bi2 + a0[nt]) * m2, L2E, -C2));
            float e3 = ex2f(fmaf((acc[it][nt][3] + bi2 + a1[nt]) * m2, L2E, -C2));
            z1 += e0 + e1;
            z2 += e2 + e3;
            float l0, l1;
            uint32_t h01 = pack2(e0, e1, l0, l1);
            *reinterpret_cast<uint32_t*>(&Ehb[(size_t)r1 * Nn + cc]) = h01;
            *reinterpret_cast<uint32_t*>(&Elb[(size_t)r1 * Nn + cc]) = pack2lo(l0, l1);
            uint32_t h23 = pack2(e2, e3, l0, l1);
            *reinterpret_cast<uint32_t*>(&Ehb[(size_t)(r1 + 8) * Nn + cc]) = h23;
            *reinterpret_cast<uint32_t*>(&Elb[(size_t)(r1 + 8) * Nn + cc]) = pack2lo(l0, l1);
        }
        z1 += __shfl_xor_sync(0xffffffffu, z1, 1);
        z1 += __shfl_xor_sync(0xffffffffu, z1, 2);
        z2 += __shfl_xor_sync(0xffffffffu, z2, 1);
        z2 += __shfl_xor_sync(0xffffffffu, z2, 2);
        if ((lane & 3) == 0) {
            atomicAdd(&Zb[r1], z1);
            atomicAdd(&Zb[r1 + 8], z2);
        }
    }
}

// ---------------------------------------------------------------------------
// Kernel E: PV GEMM on unnormalized E + normalize/blend epilogue.
// ---------------------------------------------------------------------------
__global__ void __launch_bounds__(256, 2)
pv_mma(const float* __restrict__ mask,
       const float* __restrict__ queries,
       float* __restrict__ out) {
    extern __shared__ char smem[];
    uint32_t sbase = smem_u32(smem);
    const int tid = threadIdx.x;
    const int wid = tid >> 5, lane = tid & 31;

    const int b  = blockIdx.z;
    const int c0 = blockIdx.y * 128;
    const int q0 = blockIdx.x * 128;

    float acc[4][4][4] = {};
    mma_mainloop(sbase,
                 g_vh + ((size_t)b * Cn + c0) * Nn, g_vl + ((size_t)b * Cn + c0) * Nn,
                 g_Eh + ((size_t)b * Nn + q0) * Nn, g_El + ((size_t)b * Nn + q0) * Nn,
                 Nn, Nn, Nn / 32, acc, tid, wid, lane);

    const int iBase = (wid >> 2) * 64;
    const int jBase = (wid & 3) * 32;
    const int g = lane >> 2, cp2 = (lane & 3) * 2;
    const float* mb = mask + (size_t)b * Nn;
    const float* Zb = g_Z + (size_t)b * Nn;

    int   qc[4];
    float m0[4], m1[4], iz0[4], iz1[4];
    #pragma unroll
    for (int nt = 0; nt < 4; nt++) {
        qc[nt] = q0 + jBase + nt * 8 + cp2;
        m0[nt] = mb[qc[nt]];
        m1[nt] = mb[qc[nt] + 1];
        iz0[nt] = __fdividef(1.f, Zb[qc[nt]]);
        iz1[nt] = __fdividef(1.f, Zb[qc[nt] + 1]);
    }

    #pragma unroll
    for (int it = 0; it < 4; it++) {
        int cr = c0 + iBase + it * 16 + g;
        #pragma unroll
        for (int nt = 0; nt < 4; nt++) {
            size_t gi1 = ((size_t)b * Cn + cr) * Nn + qc[nt];
            size_t gi2 = gi1 + (size_t)8 * Nn;
            float2 qa = *reinterpret_cast<const float2*>(&queries[gi1]);
            float2 qb = *reinterpret_cast<const float2*>(&queries[gi2]);
            float2 o1, o2;
            o1.x = qa.x * m0[nt] + (1.f - m0[nt]) * acc[it][nt][0] * iz0[nt];
            o1.y = qa.y * m1[nt] + (1.f - m1[nt]) * acc[it][nt][1] * iz1[nt];
            o2.x = qb.x * m0[nt] + (1.f - m0[nt]) * acc[it][nt][2] * iz0[nt];
            o2.y = qb.y * m1[nt] + (1.f - m1[nt]) * acc[it][nt][3] * iz1[nt];
            *reinterpret_cast<float2*>(&out[gi1]) = o1;
            *reinterpret_cast<float2*>(&out[gi2]) = o2;
        }
    }
}

// ---------------------------------------------------------------------------
// Launch
// ---------------------------------------------------------------------------
extern "C" void kernel_launch(void* const* d_in, const int* in_sizes, int n_in,
                              void* d_out, int out_size) {
    const float* queries = (const float*)d_in[0];
    const float* keys    = (const float*)d_in[1];
    const float* mask    = (const float*)d_in[2];
    const float* Wq      = (const float*)d_in[3];
    const float* bq      = (const float*)d_in[4];
    const float* Wk      = (const float*)d_in[5];
    const float* bk      = (const float*)d_in[6];
    const float* Wv      = (const float*)d_in[7];
    const float* bv      = (const float*)d_in[8];
    float* out = (float*)d_out;

    cudaFuncSetAttribute(proj_nk,    cudaFuncAttributeMaxDynamicSharedMemorySize, MMA_SMEM);
    cudaFuncSetAttribute(proj_cn,    cudaFuncAttributeMaxDynamicSharedMemorySize, MMA_SMEM);
    cudaFuncSetAttribute(scores_mma, cudaFuncAttributeMaxDynamicSharedMemorySize, MMA_SMEM);
    cudaFuncSetAttribute(pv_mma,     cudaFuncAttributeMaxDynamicSharedMemorySize, MMA_SMEM);

    __nv_bfloat16 *xqh, *xql, *xkh, *xkl, *Mh, *Ml, *wvh, *wvl, *yh, *yl, *vh, *vl;
    float *bz, *abw, *alpha, *beta;
    cudaGetSymbolAddress((void**)&xqh, g_xqh);
    cudaGetSymbolAddress((void**)&xql, g_xql);
    cudaGetSymbolAddress((void**)&xkh, g_xkh);
    cudaGetSymbolAddress((void**)&xkl, g_xkl);
    cudaGetSymbolAddress((void**)&Mh,  g_Mh);
    cudaGetSymbolAddress((void**)&Ml,  g_Ml);
    cudaGetSymbolAddress((void**)&wvh, g_wvh);
    cudaGetSymbolAddress((void**)&wvl, g_wvl);
    cudaGetSymbolAddress((void**)&yh,  g_yh);
    cudaGetSymbolAddress((void**)&yl,  g_yl);
    cudaGetSymbolAddress((void**)&vh,  g_vh);
    cudaGetSymbolAddress((void**)&vl,  g_vl);
    cudaGetSymbolAddress((void**)&bz,  g_bzero);
    cudaGetSymbolAddress((void**)&abw, g_abw);
    cudaGetSymbolAddress((void**)&alpha, g_alpha);
    cudaGetSymbolAddress((void**)&beta,  g_beta);

    // Weight-derived precompute first (M, aw, bw, cc), then init/splits.
    mk_kernel<<<259, 256>>>(Wq, Wk, bq, bk);
    wsplit_zero<<<641, 256>>>(Wv);

    // Input transpose + split, fused with alpha/beta dot accumulation.
    dim3 gcv(Nn / 32, Cn / 32, Bn);
    conv_split<<<gcv, 256>>>(queries, xqh, xql, abw + 256, beta);
    conv_split<<<gcv, 256>>>(keys,    xkh, xkl, abw,       alpha);

    // y = M xk (replaces q and k projections); v projection
    dim3 gnk(Cn / 128, Nn / 128, Bn);
    proj_nk<<<gnk, 256, MMA_SMEM>>>(xkh, xkl, Mh, Ml, bz, yh, yl);
    dim3 gcn(Nn / 128, Cn / 128, Bn);
    proj_cn<<<gcn, 256, MMA_SMEM>>>(wvh, wvl, xkh, xkl, bv, vh, vl);

    // Scores -> E (unnormalized exp) + Z
    dim3 gsc(Nn / 128, Nn / 128, Bn);
    scores_mma<<<gsc, 256, MMA_SMEM>>>(mask);

    // PV + normalize + blend
    dim3 gpv(Nn / 128, Cn / 128, Bn);
    pv_mma<<<gpv, 256, MMA_SMEM>>>(mask, queries, out);
}

// round 15
// speedup vs baseline: 1.0520x; 1.0016x over previous
#include <cuda_runtime.h>
#include <cuda_bf16.h>
#include <cstdint>
#include <math.h>

#define Bn 8
#define Cn 256
#define Nn 4096

#define L2E 1.4426950408889634f
#define C2  72.134752f        // 50 * log2(e)

// ---------------------------------------------------------------------------
// Scratch
// ---------------------------------------------------------------------------
__device__ __nv_bfloat16 g_xqh[(size_t)Bn * Nn * Cn];  // queries^T hi [B,N,C]
__device__ __nv_bfloat16 g_xql[(size_t)Bn * Nn * Cn];
__device__ __nv_bfloat16 g_xkh[(size_t)Bn * Nn * Cn];  // keys^T hi [B,N,C]
__device__ __nv_bfloat16 g_xkl[(size_t)Bn * Nn * Cn];
__device__ __nv_bfloat16 g_Mh[Cn * Cn];                // M = Wq^T Wk  [c][d]
__device__ __nv_bfloat16 g_Ml[Cn * Cn];
__device__ __nv_bfloat16 g_wvh[Cn * Cn];               // Wv hi [O,C]
__device__ __nv_bfloat16 g_wvl[Cn * Cn];
__device__ __nv_bfloat16 g_yh[(size_t)Bn * Nn * Cn];   // y = M xk  [B,N,C]
__device__ __nv_bfloat16 g_yl[(size_t)Bn * Nn * Cn];
__device__ __nv_bfloat16 g_vh[(size_t)Bn * Cn * Nn];   // v hi [B,C,N]
__device__ __nv_bfloat16 g_vl[(size_t)Bn * Cn * Nn];
__device__ __nv_bfloat16 g_Eh[(size_t)Bn * Nn * Nn];   // exp(s-50) hi [B,N,N]
__device__ __nv_bfloat16 g_El[(size_t)Bn * Nn * Nn];
__device__ float         g_Z [(size_t)Bn * Nn];        // row exp sums
__device__ float         g_abw[513];                   // aw[256] | bw[256] | cc
__device__ float         g_alpha[(size_t)Bn * Nn];     // per-j bias (init cc)
__device__ float         g_beta [(size_t)Bn * Nn];     // per-i bias (init 0)
__device__ float         g_bzero[Cn];                  // zero bias

// ---------------------------------------------------------------------------
// Helpers
// ---------------------------------------------------------------------------
__device__ __forceinline__ uint32_t smem_u32(const void* p) {
    uint32_t a;
    asm("{ .reg .u64 t; cvta.to.shared.u64 t, %1; cvt.u32.u64 %0, t; }"
        : "=r"(a) : "l"(p));
    return a;
}

#define SMEM_SWIZZLE_64B(off) ((off) ^ (((off) >> 3) & 0x30))

__device__ __forceinline__ void ldmx4(uint32_t* r, uint32_t a) {
    asm volatile("ldmatrix.sync.aligned.m8n8.x4.shared.b16 {%0,%1,%2,%3}, [%4];"
        : "=r"(r[0]), "=r"(r[1]), "=r"(r[2]), "=r"(r[3]) : "r"(a));
}

__device__ __forceinline__ void mma16816(float* d, const uint32_t* a,
                                         uint32_t b0, uint32_t b1) {
    asm volatile(
        "mma.sync.aligned.m16n8k16.row.col.f32.bf16.bf16.f32 "
        "{%0,%1,%2,%3}, {%4,%5,%6,%7}, {%8,%9}, {%0,%1,%2,%3};"
        : "+f"(d[0]), "+f"(d[1]), "+f"(d[2]), "+f"(d[3])
        : "r"(a[0]), "r"(a[1]), "r"(a[2]), "r"(a[3]), "r"(b0), "r"(b1));
}

__device__ __forceinline__ float ex2f(float x) {
    float y;
    asm("ex2.approx.f32 %0, %1;" : "=f"(y) : "f"(x));
    return y;
}

__device__ __forceinline__ uint32_t pack2(float a, float b, float& ra, float& rb) {
    __nv_bfloat16 ah = __float2bfloat16_rn(a);
    __nv_bfloat16 bh = __float2bfloat16_rn(b);
    ra = a - __bfloat162float(ah);
    rb = b - __bfloat162float(bh);
    __nv_bfloat162 t = __halves2bfloat162(ah, bh);
    return *reinterpret_cast<uint32_t*>(&t);
}

__device__ __forceinline__ uint32_t pack2lo(float a, float b) {
    __nv_bfloat162 t = __halves2bfloat162(__float2bfloat16_rn(a),
                                          __float2bfloat16_rn(b));
    return *reinterpret_cast<uint32_t*>(&t);
}

#define CP16(d, s) \
    asm volatile("cp.async.cg.shared.global [%0], [%1], 16;" :: "r"(d), "l"(s))
#define CP_COMMIT() asm volatile("cp.async.commit_group;" ::: "memory")
#define CP_WAIT1()  asm volatile("cp.async.wait_group 1;" ::: "memory")
#define CP_WAIT0()  asm volatile("cp.async.wait_group 0;" ::: "memory")

// ---------------------------------------------------------------------------
// GEMM building blocks: 3 stages x 4 tiles (Ah,Al,Bh,Bl) x 8KB = 96KB
// ---------------------------------------------------------------------------
#define TILE_B   8192
#define STAGE_B  (4 * TILE_B)
#define NSTAGES  3
#define MMA_SMEM (NSTAGES * STAGE_B)

__device__ __forceinline__ void cp_tile(uint32_t sdst, const __nv_bfloat16* g,
                                        int rs, int tid) {
    #pragma unroll
    for (int t = 0; t < 2; t++) {
        int u = tid + t * 256;
        int row = u >> 2, q = u & 3;
        uint32_t d = sdst + SMEM_SWIZZLE_64B((uint32_t)(row * 64 + q * 16));
        CP16(d, g + (size_t)row * rs + q * 8);
    }
}

__device__ __forceinline__ void prefetch4(uint32_t st,
                                          const __nv_bfloat16* ah,
                                          const __nv_bfloat16* al,
                                          const __nv_bfloat16* bh,
                                          const __nv_bfloat16* bl,
                                          int rsA, int rsB, int tid) {
    cp_tile(st + 0 * TILE_B, ah, rsA, tid);
    cp_tile(st + 1 * TILE_B, al, rsA, tid);
    cp_tile(st + 2 * TILE_B, bh, rsB, tid);
    cp_tile(st + 3 * TILE_B, bl, rsB, tid);
    CP_COMMIT();
}

// One K=32 chunk of MMAs (product-major, 2-way bf16 split: hh+hl+lh).
__device__ __forceinline__ void chunk_mma(uint32_t tb, uint32_t aoff,
                                          uint32_t boff, uint32_t lsw,
                                          float acc[4][4][4]) {
    #pragma unroll
    for (int ks = 0; ks < 2; ks++) {
        uint32_t kb = (uint32_t)(ks * 32);
        uint32_t ah[4][4], al[4][4];
        #pragma unroll
        for (int it = 0; it < 4; it++) {
            uint32_t o = (aoff + it * 1024 + kb) ^ lsw;
            ldmx4(ah[it], tb + o);
            ldmx4(al[it], tb + TILE_B + o);
        }
        uint32_t bh[4][2], bl[4][2];
        #pragma unroll
        for (int jp = 0; jp < 2; jp++) {
            uint32_t o = (boff + jp * 1024 + kb) ^ lsw;
            uint32_t t4[4];
            ldmx4(t4, tb + 2 * TILE_B + o);
            bh[jp * 2][0]     = t4[0]; bh[jp * 2][1]     = t4[2];
            bh[jp * 2 + 1][0] = t4[1]; bh[jp * 2 + 1][1] = t4[3];
            ldmx4(t4, tb + 3 * TILE_B + o);
            bl[jp * 2][0]     = t4[0]; bl[jp * 2][1]     = t4[2];
            bl[jp * 2 + 1][0] = t4[1]; bl[jp * 2 + 1][1] = t4[3];
        }
        #pragma unroll
        for (int it = 0; it < 4; it++)
            #pragma unroll
            for (int nt = 0; nt < 4; nt++)
                mma16816(acc[it][nt], ah[it], bh[nt][0], bh[nt][1]);
        #pragma unroll
        for (int it = 0; it < 4; it++)
            #pragma unroll
            for (int nt = 0; nt < 4; nt++)
                mma16816(acc[it][nt], ah[it], bl[nt][0], bl[nt][1]);
        #pragma unroll
        for (int it = 0; it < 4; it++)
            #pragma unroll
            for (int nt = 0; nt < 4; nt++)
                mma16816(acc[it][nt], al[it], bh[nt][0], bh[nt][1]);
    }
}

// Plain mainloop (scores, pv).
__device__ __forceinline__ void mma_mainloop(
    uint32_t sbase,
    const __nv_bfloat16* Ah, const __nv_bfloat16* Al,
    const __nv_bfloat16* Bh, const __nv_bfloat16* Bl,
    int rsA, int rsB, int nch,
    float acc[4][4][4], int tid, int wid, int lane)
{
    const int iBase = (wid >> 2) * 64;
    const int jBase = (wid & 3) * 32;
    const uint32_t lsw  = (uint32_t)(((lane >> 1) & 3) * 16);
    const uint32_t aoff = (uint32_t)((iBase + (lane & 15)) * 64 + (lane >> 4) * 16);
    const uint32_t boff = (uint32_t)((jBase + (lane & 15)) * 64 + (lane >> 4) * 16);

    #pragma unroll
    for (int p = 0; p < 2; p++)
        prefetch4(sbase + p * STAGE_B, Ah + p * 32, Al + p * 32,
                  Bh + p * 32, Bl + p * 32, rsA, rsB, tid);

    int stage = 0;
    #pragma unroll 1
    for (int c = 0; c < nch; c++) {
        if (c + 1 < nch) CP_WAIT1(); else CP_WAIT0();
        __syncthreads();
        if (c + 2 < nch) {
            int ps = stage + 2; if (ps >= NSTAGES) ps -= NSTAGES;
            int ko = (c + 2) * 32;
            prefetch4(sbase + ps * STAGE_B, Ah + ko, Al + ko,
                      Bh + ko, Bl + ko, rsA, rsB, tid);
        }
        chunk_mma(sbase + stage * STAGE_B, aoff, boff, lsw, acc);
        if (++stage == NSTAGES) stage = 0;
    }
}

// ---------------------------------------------------------------------------
// Kernel B2: M = Wq^T Wk (4-way ILP), aw = Wk^T bq, bw = Wq^T bk, cc = bq.bk.
// ---------------------------------------------------------------------------
__global__ void __launch_bounds__(256)
mk_kernel(const float* __restrict__ Wq, const float* __restrict__ Wk,
          const float* __restrict__ bq, const float* __restrict__ bk) {
    const int bid = blockIdx.x, t = threadIdx.x;
    if (bid < 256) {
        const int c = bid;
        float a0 = 0.f, a1 = 0.f, a2 = 0.f, a3 = 0.f;
        #pragma unroll 4
        for (int o = 0; o < 256; o += 4) {
            a0 += Wq[(o + 0) * 256 + c] * Wk[(o + 0) * 256 + t];
            a1 += Wq[(o + 1) * 256 + c] * Wk[(o + 1) * 256 + t];
            a2 += Wq[(o + 2) * 256 + c] * Wk[(o + 2) * 256 + t];
            a3 += Wq[(o + 3) * 256 + c] * Wk[(o + 3) * 256 + t];
        }
        float acc = (a0 + a1) + (a2 + a3);
        __nv_bfloat16 h = __float2bfloat16_rn(acc);
        g_Mh[c * 256 + t] = h;
        g_Ml[c * 256 + t] = __float2bfloat16_rn(acc - __bfloat162float(h));
    } else if (bid == 256) {
        float a0 = 0.f, a1 = 0.f;
        #pragma unroll 4
        for (int o = 0; o < 256; o += 2) {
            a0 += Wk[(o + 0) * 256 + t] * bq[o + 0];
            a1 += Wk[(o + 1) * 256 + t] * bq[o + 1];
        }
        g_abw[t] = a0 + a1;
    } else if (bid == 257) {
        float a0 = 0.f, a1 = 0.f;
        #pragma unroll 4
        for (int o = 0; o < 256; o += 2) {
            a0 += Wq[(o + 0) * 256 + t] * bk[o + 0];
            a1 += Wq[(o + 1) * 256 + t] * bk[o + 1];
        }
        g_abw[256 + t] = a0 + a1;
    } else {
        if (t < 32) {
            float s = 0.f;
            for (int o = t; o < 256; o += 32) s += bq[o] * bk[o];
            #pragma unroll
            for (int off = 16; off; off >>= 1)
                s += __shfl_xor_sync(0xffffffffu, s, off);
            if (t == 0) g_abw[512] = s;
        }
    }
}

// ---------------------------------------------------------------------------
// Kernel B: split Wv + zero Z + zero bias + init alpha (=cc) / beta (=0).
// ---------------------------------------------------------------------------
__global__ void __launch_bounds__(256)
wsplit_zero(const float* __restrict__ Wv) {
    int bid = blockIdx.x;
    if (bid < 256) {
        int idx = bid * 256 + threadIdx.x;
        float f = Wv[idx];
        __nv_bfloat16 h = __float2bfloat16_rn(f);
        g_wvh[idx] = h;
        g_wvl[idx] = __float2bfloat16_rn(f - __bfloat162float(h));
    } else if (bid < 384) {
        g_Z[(size_t)(bid - 256) * 256 + threadIdx.x] = 0.f;
    } else if (bid == 384) {
        g_bzero[threadIdx.x] = 0.f;
    } else if (bid < 513) {
        g_alpha[(size_t)(bid - 385) * 256 + threadIdx.x] = g_abw[512];
    } else {
        g_beta[(size_t)(bid - 513) * 256 + threadIdx.x] = 0.f;
    }
}

// ---------------------------------------------------------------------------
// Kernel A: transpose + bf16 hi/lo split + fused dot accumulation.
// Merged launch: z in [0, 2*Bn): which = z / Bn (0: queries->xq/beta,
// 1: keys->xk/alpha), b = z % Bn.
// ---------------------------------------------------------------------------
__global__ void __launch_bounds__(256)
conv_split(const float* __restrict__ queries, const float* __restrict__ keys) {
    __shared__ float ts[32][33];
    const int z = blockIdx.z;
    const int which = z >> 3, b = z & 7;
    const int c0 = blockIdx.y * 32, n0 = blockIdx.x * 32;
    const int r = threadIdx.x >> 5, col = threadIdx.x & 31;

    const float* x = which ? keys : queries;
    __nv_bfloat16* oh = which ? g_xkh : g_xqh;
    __nv_bfloat16* ol = which ? g_xkl : g_xql;
    const float* w = g_abw + (which ? 0 : 256);
    float* dotout = which ? g_alpha : g_beta;

    const float* xb = x + ((size_t)b * Cn + c0) * Nn + n0;
    #pragma unroll
    for (int p = 0; p < 4; p++)
        ts[r + p * 8][col] = xb[(size_t)(r + p * 8) * Nn + col];
    __syncthreads();

    __nv_bfloat16* dh = oh + ((size_t)b * Nn + n0) * Cn + c0;
    __nv_bfloat16* dl = ol + ((size_t)b * Nn + n0) * Cn + c0;
    #pragma unroll
    for (int p = 0; p < 4; p++) {
        int n = r + p * 8;
        float f = ts[col][n];
        __nv_bfloat16 h = __float2bfloat16_rn(f);
        dh[(size_t)n * Cn + col] = h;
        dl[(size_t)n * Cn + col] = __float2bfloat16_rn(f - __bfloat162float(h));
    }

    const float wv = w[c0 + col];
    #pragma unroll
    for (int p = 0; p < 4; p++) {
        int n = r + p * 8;
        float s = ts[col][n] * wv;
        #pragma unroll
        for (int off = 16; off; off >>= 1)
            s += __shfl_xor_sync(0xffffffffu, s, off);
        if (col == 0)
            atomicAdd(&dotout[(size_t)b * Nn + n0 + n], s);
    }
}

// ---------------------------------------------------------------------------
// Kernel C1: GEMM -> [N, C], CHAINED over 2 o-tiles.  Grid (1, 32, 8).
// out[n,o] = sum_c x[n,c]*W[o,c] + bias[o]
// ---------------------------------------------------------------------------
__global__ void __launch_bounds__(256, 2)
proj_nk(const __nv_bfloat16* __restrict__ xh, const __nv_bfloat16* __restrict__ xl,
        const __nv_bfloat16* __restrict__ wh, const __nv_bfloat16* __restrict__ wl,
        const float* __restrict__ bias,
        __nv_bfloat16* __restrict__ oh, __nv_bfloat16* __restrict__ ol) {
    extern __shared__ char smem[];
    uint32_t sbase = smem_u32(smem);
    const int tid = threadIdx.x;
    const int wid = tid >> 5, lane = tid & 31;

    const int b  = blockIdx.z;
    const int n0 = blockIdx.y * 128;

    const __nv_bfloat16* Ah = xh + ((size_t)b * Nn + n0) * Cn;
    const __nv_bfloat16* Al = xl + ((size_t)b * Nn + n0) * Cn;

    const int iBase = (wid >> 2) * 64;
    const int jBase = (wid & 3) * 32;
    const uint32_t lsw  = (uint32_t)(((lane >> 1) & 3) * 16);
    const uint32_t aoff = (uint32_t)((iBase + (lane & 15)) * 64 + (lane >> 4) * 16);
    const uint32_t boff = (uint32_t)((jBase + (lane & 15)) * 64 + (lane >> 4) * 16);
    const int g_ = lane >> 2, cp2 = (lane & 3) * 2;

    __nv_bfloat16* dh = oh + (size_t)b * Nn * Cn;
    __nv_bfloat16* dl = ol + (size_t)b * Nn * Cn;

    float acc[4][4][4] = {};

    const int G = 16;  // 2 tiles x 8 chunks
    #pragma unroll
    for (int p = 0; p < 2; p++)
        prefetch4(sbase + p * STAGE_B, Ah + p * 32, Al + p * 32,
                  wh + p * 32, wl + p * 32, Cn, Cn, tid);

    int stage = 0;
    #pragma unroll 1
    for (int g = 0; g < G; g++) {
        if (g + 1 < G) CP_WAIT1(); else CP_WAIT0();
        __syncthreads();
        if (g + 2 < G) {
            int ps = stage + 2; if (ps >= NSTAGES) ps -= NSTAGES;
            int gg = g + 2;
            int kc = (gg & 7) * 32;
            size_t bo = (size_t)(gg >> 3) * 128 * Cn + kc;
            prefetch4(sbase + ps * STAGE_B, Ah + kc, Al + kc,
                      wh + bo, wl + bo, Cn, Cn, tid);
        }
        chunk_mma(sbase + stage * STAGE_B, aoff, boff, lsw, acc);
        if (++stage == NSTAGES) stage = 0;

        if ((g & 7) == 7) {
            int o0 = (g >> 3) * 128;
            #pragma unroll
            for (int nt = 0; nt < 4; nt++) {
                int cc = o0 + jBase + nt * 8 + cp2;
                float b0 = bias[cc], b1 = bias[cc + 1];
                #pragma unroll
                for (int it = 0; it < 4; it++) {
                    int r1 = n0 + iBase + it * 16 + g_;
                    float l0, l1;
                    uint32_t h01 = pack2(acc[it][nt][0] + b0, acc[it][nt][1] + b1, l0, l1);
                    *reinterpret_cast<uint32_t*>(&dh[(size_t)r1 * Cn + cc]) = h01;
                    *reinterpret_cast<uint32_t*>(&dl[(size_t)r1 * Cn + cc]) = pack2lo(l0, l1);
                    uint32_t h23 = pack2(acc[it][nt][2] + b0, acc[it][nt][3] + b1, l0, l1);
                    *reinterpret_cast<uint32_t*>(&dh[(size_t)(r1 + 8) * Cn + cc]) = h23;
                    *reinterpret_cast<uint32_t*>(&dl[(size_t)(r1 + 8) * Cn + cc]) = pack2lo(l0, l1);
                }
            }
            #pragma unroll
            for (int it = 0; it < 4; it++)
                #pragma unroll
                for (int nt = 0; nt < 4; nt++)
                    #pragma unroll
                    for (int k = 0; k < 4; k++)
                        acc[it][nt][k] = 0.f;
        }
    }
}

// ---------------------------------------------------------------------------
// Kernel C2: GEMM -> [C, N] (v), CHAINED over 2 n-tiles. Grid (16, 2, 8).
// out[o,n] = sum_c W[o,c]*x[n,c] + bias[o]
// ---------------------------------------------------------------------------
__global__ void __launch_bounds__(256, 2)
proj_cn(const __nv_bfloat16* __restrict__ wh, const __nv_bfloat16* __restrict__ wl,
        const __nv_bfloat16* __restrict__ xh, const __nv_bfloat16* __restrict__ xl,
        const float* __restrict__ bias,
        __nv_bfloat16* __restrict__ oh, __nv_bfloat16* __restrict__ ol) {
    extern __shared__ char smem[];
    uint32_t sbase = smem_u32(smem);
    const int tid = threadIdx.x;
    const int wid = tid >> 5, lane = tid & 31;

    const int b   = blockIdx.z;
    const int o0  = blockIdx.y * 128;
    const int n00 = blockIdx.x * 256;

    const __nv_bfloat16* Ah = wh + (size_t)o0 * Cn;
    const __nv_bfloat16* Al = wl + (size_t)o0 * Cn;
    const __nv_bfloat16* Bh0 = xh + ((size_t)b * Nn + n00) * Cn;
    const __nv_bfloat16* Bl0 = xl + ((size_t)b * Nn + n00) * Cn;

    const int iBase = (wid >> 2) * 64;
    const int jBase = (wid & 3) * 32;
    const uint32_t lsw  = (uint32_t)(((lane >> 1) & 3) * 16);
    const uint32_t aoff = (uint32_t)((iBase + (lane & 15)) * 64 + (lane >> 4) * 16);
    const uint32_t boff = (uint32_t)((jBase + (lane & 15)) * 64 + (lane >> 4) * 16);
    const int g_ = lane >> 2, cp2 = (lane & 3) * 2;

    __nv_bfloat16* dh = oh + (size_t)b * Cn * Nn;
    __nv_bfloat16* dl = ol + (size_t)b * Cn * Nn;

    float acc[4][4][4] = {};

    const int G = 16;
    #pragma unroll
    for (int p = 0; p < 2; p++)
        prefetch4(sbase + p * STAGE_B, Ah + p * 32, Al + p * 32,
                  Bh0 + p * 32, Bl0 + p * 32, Cn, Cn, tid);

    int stage = 0;
    #pragma unroll 1
    for (int g = 0; g < G; g++) {
        if (g + 1 < G) CP_WAIT1(); else CP_WAIT0();
        __syncthreads();
        if (g + 2 < G) {
            int ps = stage + 2; if (ps >= NSTAGES) ps -= NSTAGES;
            int gg = g + 2;
            int kc = (gg & 7) * 32;
            size_t bo = (size_t)(gg >> 3) * 128 * Cn + kc;
            prefetch4(sbase + ps * STAGE_B, Ah + kc, Al + kc,
                      Bh0 + bo, Bl0 + bo, Cn, Cn, tid);
        }
        chunk_mma(sbase + stage * STAGE_B, aoff, boff, lsw, acc);
        if (++stage == NSTAGES) stage = 0;

        if ((g & 7) == 7) {
            int n0 = n00 + (g >> 3) * 128;
            #pragma unroll
            for (int it = 0; it < 4; it++) {
                int r1 = o0 + iBase + it * 16 + g_;
                float br1 = bias[r1], br2 = bias[r1 + 8];
                #pragma unroll
                for (int nt = 0; nt < 4; nt++) {
                    int cc = n0 + jBase + nt * 8 + cp2;
                    float l0, l1;
                    uint32_t h01 = pack2(acc[it][nt][0] + br1, acc[it][nt][1] + br1, l0, l1);
                    *reinterpret_cast<uint32_t*>(&dh[(size_t)r1 * Nn + cc]) = h01;
                    *reinterpret_cast<uint32_t*>(&dl[(size_t)r1 * Nn + cc]) = pack2lo(l0, l1);
                    uint32_t h23 = pack2(acc[it][nt][2] + br2, acc[it][nt][3] + br2, l0, l1);
                    *reinterpret_cast<uint32_t*>(&dh[(size_t)(r1 + 8) * Nn + cc]) = h23;
                    *reinterpret_cast<uint32_t*>(&dl[(size_t)(r1 + 8) * Nn + cc]) = pack2lo(l0, l1);
                }
            }
            #pragma unroll
            for (int it = 0; it < 4; it++)
                #pragma unroll
                for (int nt = 0; nt < 4; nt++)
                    #pragma unroll
                    for (int k = 0; k < 4; k++)
                        acc[it][nt][k] = 0.f;
        }
    }
}

// ---------------------------------------------------------------------------
// Kernel D: scores = xq . y + beta_i + alpha_j, masked; store E + Z sums.
// ---------------------------------------------------------------------------
__global__ void __launch_bounds__(256, 2)
scores_mma(const float* __restrict__ mask) {
    extern __shared__ char smem[];
    uint32_t sbase = smem_u32(smem);
    const int tid = threadIdx.x;
    const int wid = tid >> 5, lane = tid & 31;

    const int b  = blockIdx.z;
    const int i0 = blockIdx.y * 128;
    const int j0 = blockIdx.x * 128;

    float acc[4][4][4] = {};
    mma_mainloop(sbase,
                 g_xqh + ((size_t)b * Nn + i0) * Cn, g_xql + ((size_t)b * Nn + i0) * Cn,
                 g_yh  + ((size_t)b * Nn + j0) * Cn, g_yl  + ((size_t)b * Nn + j0) * Cn,
                 Cn, Cn, Cn / 32, acc, tid, wid, lane);

    const int iBase = (wid >> 2) * 64;
    const int jBase = (wid & 3) * 32;
    const int g = lane >> 2, cp2 = (lane & 3) * 2;
    const float* mb = mask + (size_t)b * Nn;
    const float* Ab = g_alpha + (size_t)b * Nn;
    const float* Bt = g_beta  + (size_t)b * Nn;
    __nv_bfloat16* Ehb = g_Eh + (size_t)b * Nn * Nn;
    __nv_bfloat16* Elb = g_El + (size_t)b * Nn * Nn;
    float* Zb = g_Z + (size_t)b * Nn;

    float a0[4], a1[4];
    #pragma unroll
    for (int nt = 0; nt < 4; nt++) {
        int cc = j0 + jBase + nt * 8 + cp2;
        a0[nt] = Ab[cc];
        a1[nt] = Ab[cc + 1];
    }

    #pragma unroll
    for (int it = 0; it < 4; it++) {
        int r1 = i0 + iBase + it * 16 + g;
        float m1 = mb[r1], m2 = mb[r1 + 8];
        float bi1 = Bt[r1], bi2 = Bt[r1 + 8];
        float z1 = 0.f, z2 = 0.f;
        #pragma unroll
        for (int nt = 0; nt < 4; nt++) {
            int cc = j0 + jBase + nt * 8 + cp2;
            float e0 = ex2f(fmaf((acc[it][nt][0] + bi1 + a0[nt]) * m1, L2E, -C2));
            float e1 = ex2f(fmaf((acc[it][nt][1] + bi1 + a1[nt]) * m1, L2E, -C2));
            float e2 = ex2f(fmaf((acc[it][nt][2] + bi2 + a0[nt]) * m2, L2E, -C2));
            float e3 = ex2f(fmaf((acc[it][nt][3] + bi2 + a1[nt]) * m2, L2E, -C2));
            z1 += e0 + e1;
            z2 += e2 + e3;
            float l0, l1;
            uint32_t h01 = pack2(e0, e1, l0, l1);
            *reinterpret_cast<uint32_t*>(&Ehb[(size_t)r1 * Nn + cc]) = h01;
            *reinterpret_cast<uint32_t*>(&Elb[(size_t)r1 * Nn + cc]) = pack2lo(l0, l1);
            uint32_t h23 = pack2(e2, e3, l0, l1);
            *reinterpret_cast<uint32_t*>(&Ehb[(size_t)(r1 + 8) * Nn + cc]) = h23;
            *reinterpret_cast<uint32_t*>(&Elb[(size_t)(r1 + 8) * Nn + cc]) = pack2lo(l0, l1);
        }
        z1 += __shfl_xor_sync(0xffffffffu, z1, 1);
        z1 += __shfl_xor_sync(0xffffffffu, z1, 2);
        z2 += __shfl_xor_sync(0xffffffffu, z2, 1);
        z2 += __shfl_xor_sync(0xffffffffu, z2, 2);
        if ((lane & 3) == 0) {
            atomicAdd(&Zb[r1], z1);
            atomicAdd(&Zb[r1 + 8], z2);
        }
    }
}

// ---------------------------------------------------------------------------
// Kernel E: PV GEMM on unnormalized E + normalize/blend epilogue.
// ---------------------------------------------------------------------------
__global__ void __launch_bounds__(256, 2)
pv_mma(const float* __restrict__ mask,
       const float* __restrict__ queries,
       float* __restrict__ out) {
    extern __shared__ char smem[];
    uint32_t sbase = smem_u32(smem);
    const int tid = threadIdx.x;
    const int wid = tid >> 5, lane = tid & 31;

    const int b  = blockIdx.z;
    const int c0 = blockIdx.y * 128;
    const int q0 = blockIdx.x * 128;

    float acc[4][4][4] = {};
    mma_mainloop(sbase,
                 g_vh + ((size_t)b * Cn + c0) * Nn, g_vl + ((size_t)b * Cn + c0) * Nn,
                 g_Eh + ((size_t)b * Nn + q0) * Nn, g_El + ((size_t)b * Nn + q0) * Nn,
                 Nn, Nn, Nn / 32, acc, tid, wid, lane);

    const int iBase = (wid >> 2) * 64;
    const int jBase = (wid & 3) * 32;
    const int g = lane >> 2, cp2 = (lane & 3) * 2;
    const float* mb = mask + (size_t)b * Nn;
    const float* Zb = g_Z + (size_t)b * Nn;

    int   qc[4];
    float m0[4], m1[4], iz0[4], iz1[4];
    #pragma unroll
    for (int nt = 0; nt < 4; nt++) {
        qc[nt] = q0 + jBase + nt * 8 + cp2;
        m0[nt] = mb[qc[nt]];
        m1[nt] = mb[qc[nt] + 1];
        iz0[nt] = __fdividef(1.f, Zb[qc[nt]]);
        iz1[nt] = __fdividef(1.f, Zb[qc[nt] + 1]);
    }

    #pragma unroll
    for (int it = 0; it < 4; it++) {
        int cr = c0 + iBase + it * 16 + g;
        #pragma unroll
        for (int nt = 0; nt < 4; nt++) {
            size_t gi1 = ((size_t)b * Cn + cr) * Nn + qc[nt];
            size_t gi2 = gi1 + (size_t)8 * Nn;
            float2 qa = *reinterpret_cast<const float2*>(&queries[gi1]);
            float2 qb = *reinterpret_cast<const float2*>(&queries[gi2]);
            float2 o1, o2;
            o1.x = qa.x * m0[nt] + (1.f - m0[nt]) * acc[it][nt][0] * iz0[nt];
            o1.y = qa.y * m1[nt] + (1.f - m1[nt]) * acc[it][nt][1] * iz1[nt];
            o2.x = qb.x * m0[nt] + (1.f - m0[nt]) * acc[it][nt][2] * iz0[nt];
            o2.y = qb.y * m1[nt] + (1.f - m1[nt]) * acc[it][nt][3] * iz1[nt];
            *reinterpret_cast<float2*>(&out[gi1]) = o1;
            *reinterpret_cast<float2*>(&out[gi2]) = o2;
        }
    }
}

// ---------------------------------------------------------------------------
// Launch
// ---------------------------------------------------------------------------
extern "C" void kernel_launch(void* const* d_in, const int* in_sizes, int n_in,
                              void* d_out, int out_size) {
    const float* queries = (const float*)d_in[0];
    const float* keys    = (const float*)d_in[1];
    const float* mask    = (const float*)d_in[2];
    const float* Wq      = (const float*)d_in[3];
    const float* bq      = (const float*)d_in[4];
    const float* Wk      = (const float*)d_in[5];
    const float* bk      = (const float*)d_in[6];
    const float* Wv      = (const float*)d_in[7];
    const float* bv      = (const float*)d_in[8];
    float* out = (float*)d_out;

    cudaFuncSetAttribute(proj_nk,    cudaFuncAttributeMaxDynamicSharedMemorySize, MMA_SMEM);
    cudaFuncSetAttribute(proj_cn,    cudaFuncAttributeMaxDynamicSharedMemorySize, MMA_SMEM);
    cudaFuncSetAttribute(scores_mma, cudaFuncAttributeMaxDynamicSharedMemorySize, MMA_SMEM);
    cudaFuncSetAttribute(pv_mma,     cudaFuncAttributeMaxDynamicSharedMemorySize, MMA_SMEM);

    __nv_bfloat16 *xkh, *xkl, *Mh, *Ml, *wvh, *wvl, *yh, *yl, *vh, *vl;
    float* bz;
    cudaGetSymbolAddress((void**)&xkh, g_xkh);
    cudaGetSymbolAddress((void**)&xkl, g_xkl);
    cudaGetSymbolAddress((void**)&Mh,  g_Mh);
    cudaGetSymbolAddress((void**)&Ml,  g_Ml);
    cudaGetSymbolAddress((void**)&wvh, g_wvh);
    cudaGetSymbolAddress((void**)&wvl, g_wvl);
    cudaGetSymbolAddress((void**)&yh,  g_yh);
    cudaGetSymbolAddress((void**)&yl,  g_yl);
    cudaGetSymbolAddress((void**)&vh,  g_vh);
    cudaGetSymbolAddress((void**)&vl,  g_vl);
    cudaGetSymbolAddress((void**)&bz,  g_bzero);

    // Weight-derived precompute (M, aw, bw, cc), then init/splits.
    mk_kernel<<<259, 256>>>(Wq, Wk, bq, bk);
    wsplit_zero<<<641, 256>>>(Wv);

    // Input transpose + split + alpha/beta dots (merged q+k launch).
    dim3 gcv(Nn / 32, Cn / 32, 2 * Bn);
    conv_split<<<gcv, 256>>>(queries, keys);

    // y = M xk (replaces q/k projections); v projection. Chained tiles.
    dim3 gnk(1, Nn / 128, Bn);
    proj_nk<<<gnk, 256, MMA_SMEM>>>(xkh, xkl, Mh, Ml, bz, yh, yl);
    dim3 gcn(Nn / 256, Cn / 128, Bn);
    proj_cn<<<gcn, 256, MMA_SMEM>>>(wvh, wvl, xkh, xkl, bv, vh, vl);

    // Scores -> E (unnormalized exp) + Z
    dim3 gsc(Nn / 128, Nn / 128, Bn);
    scores_mma<<<gsc, 256, MMA_SMEM>>>(mask);

    // PV + normalize + blend
    dim3 gpv(Nn / 128, Cn / 128, Bn);
    pv_mma<<<gpv, 256, MMA_SMEM>>>(mask, queries, out);
}

// round 16
// speedup vs baseline: 1.0612x; 1.0088x over previous
#include <cuda_runtime.h>
#include <cuda_bf16.h>
#include <cstdint>
#include <math.h>

#define Bn 8
#define Cn 256
#define Nn 4096

#define L2E 1.4426950408889634f
#define C2  72.134752f        // 50 * log2(e)

// ---------------------------------------------------------------------------
// Scratch
// ---------------------------------------------------------------------------
__device__ __nv_bfloat16 g_xqh[(size_t)Bn * Nn * Cn];  // queries^T hi [B,N,C]
__device__ __nv_bfloat16 g_xql[(size_t)Bn * Nn * Cn];
__device__ __nv_bfloat16 g_xkh[(size_t)Bn * Nn * Cn];  // keys^T hi [B,N,C]
__device__ __nv_bfloat16 g_xkl[(size_t)Bn * Nn * Cn];
__device__ __nv_bfloat16 g_Mh[Cn * Cn];                // M = Wq^T Wk  [c][d]
__device__ __nv_bfloat16 g_Ml[Cn * Cn];
__device__ __nv_bfloat16 g_wvh[Cn * Cn];               // Wv hi [O,C]
__device__ __nv_bfloat16 g_wvl[Cn * Cn];
__device__ __nv_bfloat16 g_yh[(size_t)Bn * Nn * Cn];   // y = M xk  [B,N,C]
__device__ __nv_bfloat16 g_yl[(size_t)Bn * Nn * Cn];
__device__ __nv_bfloat16 g_vh[(size_t)Bn * Cn * Nn];   // v hi [B,C,N]
__device__ __nv_bfloat16 g_vl[(size_t)Bn * Cn * Nn];
__device__ __nv_bfloat16 g_Eh[(size_t)Bn * Nn * Nn];   // exp(s-50) hi [B,N,N]
__device__ __nv_bfloat16 g_El[(size_t)Bn * Nn * Nn];
__device__ float         g_Z [(size_t)Bn * Nn];        // row exp sums
__device__ float         g_abw[513];                   // aw[256] | bw[256] | cc
__device__ float         g_alpha[(size_t)Bn * Nn];     // per-j bias (init 0)
__device__ float         g_beta [(size_t)Bn * Nn];     // per-i bias (init 0)

// ---------------------------------------------------------------------------
// Helpers
// ---------------------------------------------------------------------------
__device__ __forceinline__ uint32_t smem_u32(const void* p) {
    uint32_t a;
    asm("{ .reg .u64 t; cvta.to.shared.u64 t, %1; cvt.u32.u64 %0, t; }"
        : "=r"(a) : "l"(p));
    return a;
}

#define SMEM_SWIZZLE_64B(off) ((off) ^ (((off) >> 3) & 0x30))

__device__ __forceinline__ void ldmx4(uint32_t* r, uint32_t a) {
    asm volatile("ldmatrix.sync.aligned.m8n8.x4.shared.b16 {%0,%1,%2,%3}, [%4];"
        : "=r"(r[0]), "=r"(r[1]), "=r"(r[2]), "=r"(r[3]) : "r"(a));
}

__device__ __forceinline__ void mma16816(float* d, const uint32_t* a,
                                         uint32_t b0, uint32_t b1) {
    asm volatile(
        "mma.sync.aligned.m16n8k16.row.col.f32.bf16.bf16.f32 "
        "{%0,%1,%2,%3}, {%4,%5,%6,%7}, {%8,%9}, {%0,%1,%2,%3};"
        : "+f"(d[0]), "+f"(d[1]), "+f"(d[2]), "+f"(d[3])
        : "r"(a[0]), "r"(a[1]), "r"(a[2]), "r"(a[3]), "r"(b0), "r"(b1));
}

__device__ __forceinline__ float ex2f(float x) {
    float y;
    asm("ex2.approx.f32 %0, %1;" : "=f"(y) : "f"(x));
    return y;
}

__device__ __forceinline__ uint32_t pack2(float a, float b, float& ra, float& rb) {
    __nv_bfloat16 ah = __float2bfloat16_rn(a);
    __nv_bfloat16 bh = __float2bfloat16_rn(b);
    ra = a - __bfloat162float(ah);
    rb = b - __bfloat162float(bh);
    __nv_bfloat162 t = __halves2bfloat162(ah, bh);
    return *reinterpret_cast<uint32_t*>(&t);
}

__device__ __forceinline__ uint32_t pack2lo(float a, float b) {
    __nv_bfloat162 t = __halves2bfloat162(__float2bfloat16_rn(a),
                                          __float2bfloat16_rn(b));
    return *reinterpret_cast<uint32_t*>(&t);
}

#define CP16(d, s) \
    asm volatile("cp.async.cg.shared.global [%0], [%1], 16;" :: "r"(d), "l"(s))
#define CP_COMMIT() asm volatile("cp.async.commit_group;" ::: "memory")
#define CP_WAIT1()  asm volatile("cp.async.wait_group 1;" ::: "memory")
#define CP_WAIT0()  asm volatile("cp.async.wait_group 0;" ::: "memory")

// ---------------------------------------------------------------------------
// GEMM building blocks: 3 stages x 4 tiles (Ah,Al,Bh,Bl) x 8KB = 96KB
// ---------------------------------------------------------------------------
#define TILE_B   8192
#define STAGE_B  (4 * TILE_B)
#define NSTAGES  3
#define MMA_SMEM (NSTAGES * STAGE_B)

__device__ __forceinline__ void cp_tile(uint32_t sdst, const __nv_bfloat16* g,
                                        int rs, int tid) {
    #pragma unroll
    for (int t = 0; t < 2; t++) {
        int u = tid + t * 256;
        int row = u >> 2, q = u & 3;
        uint32_t d = sdst + SMEM_SWIZZLE_64B((uint32_t)(row * 64 + q * 16));
        CP16(d, g + (size_t)row * rs + q * 8);
    }
}

__device__ __forceinline__ void prefetch4(uint32_t st,
                                          const __nv_bfloat16* ah,
                                          const __nv_bfloat16* al,
                                          const __nv_bfloat16* bh,
                                          const __nv_bfloat16* bl,
                                          int rsA, int rsB, int tid) {
    cp_tile(st + 0 * TILE_B, ah, rsA, tid);
    cp_tile(st + 1 * TILE_B, al, rsA, tid);
    cp_tile(st + 2 * TILE_B, bh, rsB, tid);
    cp_tile(st + 3 * TILE_B, bl, rsB, tid);
    CP_COMMIT();
}

// One K=32 chunk of MMAs (product-major, 2-way bf16 split: hh+hl+lh).
__device__ __forceinline__ void chunk_mma(uint32_t tb, uint32_t aoff,
                                          uint32_t boff, uint32_t lsw,
                                          float acc[4][4][4]) {
    #pragma unroll
    for (int ks = 0; ks < 2; ks++) {
        uint32_t kb = (uint32_t)(ks * 32);
        uint32_t ah[4][4], al[4][4];
        #pragma unroll
        for (int it = 0; it < 4; it++) {
            uint32_t o = (aoff + it * 1024 + kb) ^ lsw;
            ldmx4(ah[it], tb + o);
            ldmx4(al[it], tb + TILE_B + o);
        }
        uint32_t bh[4][2], bl[4][2];
        #pragma unroll
        for (int jp = 0; jp < 2; jp++) {
            uint32_t o = (boff + jp * 1024 + kb) ^ lsw;
            uint32_t t4[4];
            ldmx4(t4, tb + 2 * TILE_B + o);
            bh[jp * 2][0]     = t4[0]; bh[jp * 2][1]     = t4[2];
            bh[jp * 2 + 1][0] = t4[1]; bh[jp * 2 + 1][1] = t4[3];
            ldmx4(t4, tb + 3 * TILE_B + o);
            bl[jp * 2][0]     = t4[0]; bl[jp * 2][1]     = t4[2];
            bl[jp * 2 + 1][0] = t4[1]; bl[jp * 2 + 1][1] = t4[3];
        }
        #pragma unroll
        for (int it = 0; it < 4; it++)
            #pragma unroll
            for (int nt = 0; nt < 4; nt++)
                mma16816(acc[it][nt], ah[it], bh[nt][0], bh[nt][1]);
        #pragma unroll
        for (int it = 0; it < 4; it++)
            #pragma unroll
            for (int nt = 0; nt < 4; nt++)
                mma16816(acc[it][nt], ah[it], bl[nt][0], bl[nt][1]);
        #pragma unroll
        for (int it = 0; it < 4; it++)
            #pragma unroll
            for (int nt = 0; nt < 4; nt++)
                mma16816(acc[it][nt], al[it], bh[nt][0], bh[nt][1]);
    }
}

// Plain mainloop (scores, pv).
__device__ __forceinline__ void mma_mainloop(
    uint32_t sbase,
    const __nv_bfloat16* Ah, const __nv_bfloat16* Al,
    const __nv_bfloat16* Bh, const __nv_bfloat16* Bl,
    int rsA, int rsB, int nch,
    float acc[4][4][4], int tid, int wid, int lane)
{
    const int iBase = (wid >> 2) * 64;
    const int jBase = (wid & 3) * 32;
    const uint32_t lsw  = (uint32_t)(((lane >> 1) & 3) * 16);
    const uint32_t aoff = (uint32_t)((iBase + (lane & 15)) * 64 + (lane >> 4) * 16);
    const uint32_t boff = (uint32_t)((jBase + (lane & 15)) * 64 + (lane >> 4) * 16);

    #pragma unroll
    for (int p = 0; p < 2; p++)
        prefetch4(sbase + p * STAGE_B, Ah + p * 32, Al + p * 32,
                  Bh + p * 32, Bl + p * 32, rsA, rsB, tid);

    int stage = 0;
    #pragma unroll 1
    for (int c = 0; c < nch; c++) {
        if (c + 1 < nch) CP_WAIT1(); else CP_WAIT0();
        __syncthreads();
        if (c + 2 < nch) {
            int ps = stage + 2; if (ps >= NSTAGES) ps -= NSTAGES;
            int ko = (c + 2) * 32;
            prefetch4(sbase + ps * STAGE_B, Ah + ko, Al + ko,
                      Bh + ko, Bl + ko, rsA, rsB, tid);
        }
        chunk_mma(sbase + stage * STAGE_B, aoff, boff, lsw, acc);
        if (++stage == NSTAGES) stage = 0;
    }
}

// ---------------------------------------------------------------------------
// Kernel B: ALL weight-derived precompute + zero-init, one launch.
// blocks: [0,256) M | 256 aw | 257 bw | 258 cc | [259,515) Wv split |
//         [515,643) Z=0 | [643,771) alpha=0 | [771,899) beta=0
// ---------------------------------------------------------------------------
__global__ void __launch_bounds__(256)
prep_kernel(const float* __restrict__ Wq, const float* __restrict__ Wk,
            const float* __restrict__ bq, const float* __restrict__ bk,
            const float* __restrict__ Wv) {
    const int bid = blockIdx.x, t = threadIdx.x;
    if (bid < 256) {
        const int c = bid;
        float a0 = 0.f, a1 = 0.f, a2 = 0.f, a3 = 0.f;
        #pragma unroll 4
        for (int o = 0; o < 256; o += 4) {
            a0 += Wq[(o + 0) * 256 + c] * Wk[(o + 0) * 256 + t];
            a1 += Wq[(o + 1) * 256 + c] * Wk[(o + 1) * 256 + t];
            a2 += Wq[(o + 2) * 256 + c] * Wk[(o + 2) * 256 + t];
            a3 += Wq[(o + 3) * 256 + c] * Wk[(o + 3) * 256 + t];
        }
        float acc = (a0 + a1) + (a2 + a3);
        __nv_bfloat16 h = __float2bfloat16_rn(acc);
        g_Mh[c * 256 + t] = h;
        g_Ml[c * 256 + t] = __float2bfloat16_rn(acc - __bfloat162float(h));
    } else if (bid == 256) {
        float a0 = 0.f, a1 = 0.f;
        #pragma unroll 4
        for (int o = 0; o < 256; o += 2) {
            a0 += Wk[(o + 0) * 256 + t] * bq[o + 0];
            a1 += Wk[(o + 1) * 256 + t] * bq[o + 1];
        }
        g_abw[t] = a0 + a1;
    } else if (bid == 257) {
        float a0 = 0.f, a1 = 0.f;
        #pragma unroll 4
        for (int o = 0; o < 256; o += 2) {
            a0 += Wq[(o + 0) * 256 + t] * bk[o + 0];
            a1 += Wq[(o + 1) * 256 + t] * bk[o + 1];
        }
        g_abw[256 + t] = a0 + a1;
    } else if (bid == 258) {
        if (t < 32) {
            float s = 0.f;
            for (int o = t; o < 256; o += 32) s += bq[o] * bk[o];
            #pragma unroll
            for (int off = 16; off; off >>= 1)
                s += __shfl_xor_sync(0xffffffffu, s, off);
            if (t == 0) g_abw[512] = s;
        }
    } else if (bid < 515) {
        int idx = (bid - 259) * 256 + t;
        float f = Wv[idx];
        __nv_bfloat16 h = __float2bfloat16_rn(f);
        g_wvh[idx] = h;
        g_wvl[idx] = __float2bfloat16_rn(f - __bfloat162float(h));
    } else if (bid < 643) {
        g_Z[(size_t)(bid - 515) * 256 + t] = 0.f;
    } else if (bid < 771) {
        g_alpha[(size_t)(bid - 643) * 256 + t] = 0.f;
    } else {
        g_beta[(size_t)(bid - 771) * 256 + t] = 0.f;
    }
}

// ---------------------------------------------------------------------------
// Kernel A: transpose + bf16 hi/lo split + fused dot accumulation.
// z in [0, 2*Bn): which = z >> 3 (0: queries->xq/beta, 1: keys->xk/alpha).
// ---------------------------------------------------------------------------
__global__ void __launch_bounds__(256)
conv_split(const float* __restrict__ queries, const float* __restrict__ keys) {
    __shared__ float ts[32][33];
    const int z = blockIdx.z;
    const int which = z >> 3, b = z & 7;
    const int c0 = blockIdx.y * 32, n0 = blockIdx.x * 32;
    const int r = threadIdx.x >> 5, col = threadIdx.x & 31;

    const float* x = which ? keys : queries;
    __nv_bfloat16* oh = which ? g_xkh : g_xqh;
    __nv_bfloat16* ol = which ? g_xkl : g_xql;
    const float* w = g_abw + (which ? 0 : 256);
    float* dotout = which ? g_alpha : g_beta;

    const float* xb = x + ((size_t)b * Cn + c0) * Nn + n0;
    #pragma unroll
    for (int p = 0; p < 4; p++)
        ts[r + p * 8][col] = xb[(size_t)(r + p * 8) * Nn + col];
    __syncthreads();

    __nv_bfloat16* dh = oh + ((size_t)b * Nn + n0) * Cn + c0;
    __nv_bfloat16* dl = ol + ((size_t)b * Nn + n0) * Cn + c0;
    #pragma unroll
    for (int p = 0; p < 4; p++) {
        int n = r + p * 8;
        float f = ts[col][n];
        __nv_bfloat16 h = __float2bfloat16_rn(f);
        dh[(size_t)n * Cn + col] = h;
        dl[(size_t)n * Cn + col] = __float2bfloat16_rn(f - __bfloat162float(h));
    }

    const float wv = w[c0 + col];
    #pragma unroll
    for (int p = 0; p < 4; p++) {
        int n = r + p * 8;
        float s = ts[col][n] * wv;
        #pragma unroll
        for (int off = 16; off; off >>= 1)
            s += __shfl_xor_sync(0xffffffffu, s, off);
        if (col == 0)
            atomicAdd(&dotout[(size_t)b * Nn + n0 + n], s);
    }
}

// ---------------------------------------------------------------------------
// Kernel C: merged projection GEMMs, one launch. Grid (32, 1, 16).
// z < 8:  y = M xk  -> [N, C], chained over 2 o-tiles, no bias.
// z >= 8: v = Wv xk -> [C, N], chained over 2 n-tiles, bias bv.
// ---------------------------------------------------------------------------
__global__ void __launch_bounds__(256, 2)
proj_both(const float* __restrict__ bv) {
    extern __shared__ char smem[];
    uint32_t sbase = smem_u32(smem);
    const int tid = threadIdx.x;
    const int wid = tid >> 5, lane = tid & 31;

    const int iBase = (wid >> 2) * 64;
    const int jBase = (wid & 3) * 32;
    const uint32_t lsw  = (uint32_t)(((lane >> 1) & 3) * 16);
    const uint32_t aoff = (uint32_t)((iBase + (lane & 15)) * 64 + (lane >> 4) * 16);
    const uint32_t boff = (uint32_t)((jBase + (lane & 15)) * 64 + (lane >> 4) * 16);
    const int g_ = lane >> 2, cp2 = (lane & 3) * 2;

    float acc[4][4][4] = {};
    const int G = 16;

    if (blockIdx.z < 8) {
        // ---- y = M xk : out [N, C] ----
        const int b  = blockIdx.z;
        const int n0 = blockIdx.x * 128;
        const __nv_bfloat16* Ah = g_xkh + ((size_t)b * Nn + n0) * Cn;
        const __nv_bfloat16* Al = g_xkl + ((size_t)b * Nn + n0) * Cn;
        __nv_bfloat16* dh = g_yh + (size_t)b * Nn * Cn;
        __nv_bfloat16* dl = g_yl + (size_t)b * Nn * Cn;

        #pragma unroll
        for (int p = 0; p < 2; p++)
            prefetch4(sbase + p * STAGE_B, Ah + p * 32, Al + p * 32,
                      g_Mh + p * 32, g_Ml + p * 32, Cn, Cn, tid);

        int stage = 0;
        #pragma unroll 1
        for (int g = 0; g < G; g++) {
            if (g + 1 < G) CP_WAIT1(); else CP_WAIT0();
            __syncthreads();
            if (g + 2 < G) {
                int ps = stage + 2; if (ps >= NSTAGES) ps -= NSTAGES;
                int gg = g + 2;
                int kc = (gg & 7) * 32;
                size_t bo = (size_t)(gg >> 3) * 128 * Cn + kc;
                prefetch4(sbase + ps * STAGE_B, Ah + kc, Al + kc,
                          g_Mh + bo, g_Ml + bo, Cn, Cn, tid);
            }
            chunk_mma(sbase + stage * STAGE_B, aoff, boff, lsw, acc);
            if (++stage == NSTAGES) stage = 0;

            if ((g & 7) == 7) {
                int o0 = (g >> 3) * 128;
                #pragma unroll
                for (int nt = 0; nt < 4; nt++) {
                    int cc = o0 + jBase + nt * 8 + cp2;
                    #pragma unroll
                    for (int it = 0; it < 4; it++) {
                        int r1 = n0 + iBase + it * 16 + g_;
                        float l0, l1;
                        uint32_t h01 = pack2(acc[it][nt][0], acc[it][nt][1], l0, l1);
                        *reinterpret_cast<uint32_t*>(&dh[(size_t)r1 * Cn + cc]) = h01;
                        *reinterpret_cast<uint32_t*>(&dl[(size_t)r1 * Cn + cc]) = pack2lo(l0, l1);
                        uint32_t h23 = pack2(acc[it][nt][2], acc[it][nt][3], l0, l1);
                        *reinterpret_cast<uint32_t*>(&dh[(size_t)(r1 + 8) * Cn + cc]) = h23;
                        *reinterpret_cast<uint32_t*>(&dl[(size_t)(r1 + 8) * Cn + cc]) = pack2lo(l0, l1);
                    }
                }
                #pragma unroll
                for (int it = 0; it < 4; it++)
                    #pragma unroll
                    for (int nt = 0; nt < 4; nt++)
                        #pragma unroll
                        for (int k = 0; k < 4; k++)
                            acc[it][nt][k] = 0.f;
            }
        }
    } else {
        // ---- v = Wv xk : out [C, N] ----
        const int b   = blockIdx.z - 8;
        const int o0  = (blockIdx.x >> 4) * 128;
        const int n00 = (blockIdx.x & 15) * 256;
        const __nv_bfloat16* Ah = g_wvh + (size_t)o0 * Cn;
        const __nv_bfloat16* Al = g_wvl + (size_t)o0 * Cn;
        const __nv_bfloat16* Bh0 = g_xkh + ((size_t)b * Nn + n00) * Cn;
        const __nv_bfloat16* Bl0 = g_xkl + ((size_t)b * Nn + n00) * Cn;
        __nv_bfloat16* dh = g_vh + (size_t)b * Cn * Nn;
        __nv_bfloat16* dl = g_vl + (size_t)b * Cn * Nn;

        #pragma unroll
        for (int p = 0; p < 2; p++)
            prefetch4(sbase + p * STAGE_B, Ah + p * 32, Al + p * 32,
                      Bh0 + p * 32, Bl0 + p * 32, Cn, Cn, tid);

        int stage = 0;
        #pragma unroll 1
        for (int g = 0; g < G; g++) {
            if (g + 1 < G) CP_WAIT1(); else CP_WAIT0();
            __syncthreads();
            if (g + 2 < G) {
                int ps = stage + 2; if (ps >= NSTAGES) ps -= NSTAGES;
                int gg = g + 2;
                int kc = (gg & 7) * 32;
                size_t bo = (size_t)(gg >> 3) * 128 * Cn + kc;
                prefetch4(sbase + ps * STAGE_B, Ah + kc, Al + kc,
                          Bh0 + bo, Bl0 + bo, Cn, Cn, tid);
            }
            chunk_mma(sbase + stage * STAGE_B, aoff, boff, lsw, acc);
            if (++stage == NSTAGES) stage = 0;

            if ((g & 7) == 7) {
                int n0 = n00 + (g >> 3) * 128;
                #pragma unroll
                for (int it = 0; it < 4; it++) {
                    int r1 = o0 + iBase + it * 16 + g_;
                    float br1 = bv[r1], br2 = bv[r1 + 8];
                    #pragma unroll
                    for (int nt = 0; nt < 4; nt++) {
                        int cc = n0 + jBase + nt * 8 + cp2;
                        float l0, l1;
                        uint32_t h01 = pack2(acc[it][nt][0] + br1, acc[it][nt][1] + br1, l0, l1);
                        *reinterpret_cast<uint32_t*>(&dh[(size_t)r1 * Nn + cc]) = h01;
                        *reinterpret_cast<uint32_t*>(&dl[(size_t)r1 * Nn + cc]) = pack2lo(l0, l1);
                        uint32_t h23 = pack2(acc[it][nt][2] + br2, acc[it][nt][3] + br2, l0, l1);
                        *reinterpret_cast<uint32_t*>(&dh[(size_t)(r1 + 8) * Nn + cc]) = h23;
                        *reinterpret_cast<uint32_t*>(&dl[(size_t)(r1 + 8) * Nn + cc]) = pack2lo(l0, l1);
                    }
                }
                #pragma unroll
                for (int it = 0; it < 4; it++)
                    #pragma unroll
                    for (int nt = 0; nt < 4; nt++)
                        #pragma unroll
                        for (int k = 0; k < 4; k++)
                            acc[it][nt][k] = 0.f;
            }
        }
    }
}

// ---------------------------------------------------------------------------
// Kernel D: scores = xq . y + beta_i + alpha_j + cc, masked; store E + Z.
// ---------------------------------------------------------------------------
__global__ void __launch_bounds__(256, 2)
scores_mma(const float* __restrict__ mask) {
    extern __shared__ char smem[];
    uint32_t sbase = smem_u32(smem);
    const int tid = threadIdx.x;
    const int wid = tid >> 5, lane = tid & 31;

    const int b  = blockIdx.z;
    const int i0 = blockIdx.y * 128;
    const int j0 = blockIdx.x * 128;

    float acc[4][4][4] = {};
    mma_mainloop(sbase,
                 g_xqh + ((size_t)b * Nn + i0) * Cn, g_xql + ((size_t)b * Nn + i0) * Cn,
                 g_yh  + ((size_t)b * Nn + j0) * Cn, g_yl  + ((size_t)b * Nn + j0) * Cn,
                 Cn, Cn, Cn / 32, acc, tid, wid, lane);

    const int iBase = (wid >> 2) * 64;
    const int jBase = (wid & 3) * 32;
    const int g = lane >> 2, cp2 = (lane & 3) * 2;
    const float* mb = mask + (size_t)b * Nn;
    const float* Ab = g_alpha + (size_t)b * Nn;
    const float* Bt = g_beta  + (size_t)b * Nn;
    const float ccv = g_abw[512];
    __nv_bfloat16* Ehb = g_Eh + (size_t)b * Nn * Nn;
    __nv_bfloat16* Elb = g_El + (size_t)b * Nn * Nn;
    float* Zb = g_Z + (size_t)b * Nn;

    float a0[4], a1[4];
    #pragma unroll
    for (int nt = 0; nt < 4; nt++) {
        int cc = j0 + jBase + nt * 8 + cp2;
        a0[nt] = Ab[cc];
        a1[nt] = Ab[cc + 1];
    }

    #pragma unroll
    for (int it = 0; it < 4; it++) {
        int r1 = i0 + iBase + it * 16 + g;
        float m1 = mb[r1], m2 = mb[r1 + 8];
        float bi1 = Bt[r1] + ccv, bi2 = Bt[r1 + 8] + ccv;
        float z1 = 0.f, z2 = 0.f;
        #pragma unroll
        for (int nt = 0; nt < 4; nt++) {
            int cc = j0 + jBase + nt * 8 + cp2;
            float e0 = ex2f(fmaf((acc[it][nt][0] + bi1 + a0[nt]) * m1, L2E, -C2));
            float e1 = ex2f(fmaf((acc[it][nt][1] + bi1 + a1[nt]) * m1, L2E, -C2));
            float e2 = ex2f(fmaf((acc[it][nt][2] + bi2 + a0[nt]) * m2, L2E, -C2));
            float e3 = ex2f(fmaf((acc[it][nt][3] + bi2 + a1[nt]) * m2, L2E, -C2));
            z1 += e0 + e1;
            z2 += e2 + e3;
            float l0, l1;
            uint32_t h01 = pack2(e0, e1, l0, l1);
            *reinterpret_cast<uint32_t*>(&Ehb[(size_t)r1 * Nn + cc]) = h01;
            *reinterpret_cast<uint32_t*>(&Elb[(size_t)r1 * Nn + cc]) = pack2lo(l0, l1);
            uint32_t h23 = pack2(e2, e3, l0, l1);
            *reinterpret_cast<uint32_t*>(&Ehb[(size_t)(r1 + 8) * Nn + cc]) = h23;
            *reinterpret_cast<uint32_t*>(&Elb[(size_t)(r1 + 8) * Nn + cc]) = pack2lo(l0, l1);
        }
        z1 += __shfl_xor_sync(0xffffffffu, z1, 1);
        z1 += __shfl_xor_sync(0xffffffffu, z1, 2);
        z2 += __shfl_xor_sync(0xffffffffu, z2, 1);
        z2 += __shfl_xor_sync(0xffffffffu, z2, 2);
        if ((lane & 3) == 0) {
            atomicAdd(&Zb[r1], z1);
            atomicAdd(&Zb[r1 + 8], z2);
        }
    }
}

// ---------------------------------------------------------------------------
// Kernel E: PV GEMM on unnormalized E + normalize/blend epilogue.
// ---------------------------------------------------------------------------
__global__ void __launch_bounds__(256, 2)
pv_mma(const float* __restrict__ mask,
       const float* __restrict__ queries,
       float* __restrict__ out) {
    extern __shared__ char smem[];
    uint32_t sbase = smem_u32(smem);
    const int tid = threadIdx.x;
    const int wid = tid >> 5, lane = tid & 31;

    const int b  = blockIdx.z;
    const int c0 = blockIdx.y * 128;
    const int q0 = blockIdx.x * 128;

    float acc[4][4][4] = {};
    mma_mainloop(sbase,
                 g_vh + ((size_t)b * Cn + c0) * Nn, g_vl + ((size_t)b * Cn + c0) * Nn,
                 g_Eh + ((size_t)b * Nn + q0) * Nn, g_El + ((size_t)b * Nn + q0) * Nn,
                 Nn, Nn, Nn / 32, acc, tid, wid, lane);

    const int iBase = (wid >> 2) * 64;
    const int jBase = (wid & 3) * 32;
    const int g = lane >> 2, cp2 = (lane & 3) * 2;
    const float* mb = mask + (size_t)b * Nn;
    const float* Zb = g_Z + (size_t)b * Nn;

    int   qc[4];
    float m0[4], m1[4], iz0[4], iz1[4];
    #pragma unroll
    for (int nt = 0; nt < 4; nt++) {
        qc[nt] = q0 + jBase + nt * 8 + cp2;
        m0[nt] = mb[qc[nt]];
        m1[nt] = mb[qc[nt] + 1];
        iz0[nt] = __fdividef(1.f, Zb[qc[nt]]);
        iz1[nt] = __fdividef(1.f, Zb[qc[nt] + 1]);
    }

    #pragma unroll
    for (int it = 0; it < 4; it++) {
        int cr = c0 + iBase + it * 16 + g;
        #pragma unroll
        for (int nt = 0; nt < 4; nt++) {
            size_t gi1 = ((size_t)b * Cn + cr) * Nn + qc[nt];
            size_t gi2 = gi1 + (size_t)8 * Nn;
            float2 qa = *reinterpret_cast<const float2*>(&queries[gi1]);
            float2 qb = *reinterpret_cast<const float2*>(&queries[gi2]);
            float2 o1, o2;
            o1.x = qa.x * m0[nt] + (1.f - m0[nt]) * acc[it][nt][0] * iz0[nt];
            o1.y = qa.y * m1[nt] + (1.f - m1[nt]) * acc[it][nt][1] * iz1[nt];
            o2.x = qb.x * m0[nt] + (1.f - m0[nt]) * acc[it][nt][2] * iz0[nt];
            o2.y = qb.y * m1[nt] + (1.f - m1[nt]) * acc[it][nt][3] * iz1[nt];
            *reinterpret_cast<float2*>(&out[gi1]) = o1;
            *reinterpret_cast<float2*>(&out[gi2]) = o2;
        }
    }
}

// ---------------------------------------------------------------------------
// Launch
// ---------------------------------------------------------------------------
extern "C" void kernel_launch(void* const* d_in, const int* in_sizes, int n_in,
                              void* d_out, int out_size) {
    const float* queries = (const float*)d_in[0];
    const float* keys    = (const float*)d_in[1];
    const float* mask    = (const float*)d_in[2];
    const float* Wq      = (const float*)d_in[3];
    const float* bq      = (const float*)d_in[4];
    const float* Wk      = (const float*)d_in[5];
    const float* bk      = (const float*)d_in[6];
    const float* Wv      = (const float*)d_in[7];
    const float* bv      = (const float*)d_in[8];
    float* out = (float*)d_out;

    cudaFuncSetAttribute(proj_both,  cudaFuncAttributeMaxDynamicSharedMemorySize, MMA_SMEM);
    cudaFuncSetAttribute(scores_mma, cudaFuncAttributeMaxDynamicSharedMemorySize, MMA_SMEM);
    cudaFuncSetAttribute(pv_mma,     cudaFuncAttributeMaxDynamicSharedMemorySize, MMA_SMEM);

    // All weight-derived precompute + zero-init in one launch.
    prep_kernel<<<899, 256>>>(Wq, Wk, bq, bk, Wv);

    // Input transpose + split + alpha/beta dots (merged q+k launch).
    dim3 gcv(Nn / 32, Cn / 32, 2 * Bn);
    conv_split<<<gcv, 256>>>(queries, keys);

    // Merged projection GEMMs: y = M xk and v = Wv xk in one launch.
    dim3 gpj(32, 1, 16);
    proj_both<<<gpj, 256, MMA_SMEM>>>(bv);

    // Scores -> E (unnormalized exp) + Z
    dim3 gsc(Nn / 128, Nn / 128, Bn);
    scores_mma<<<gsc, 256, MMA_SMEM>>>(mask);

    // PV + normalize + blend
    dim3 gpv(Nn / 128, Cn / 128, Bn);
    pv_mma<<<gpv, 256, MMA_SMEM>>>(mask, queries, out);
}

// round 17
// speedup vs baseline: 1.2581x; 1.1855x over previous
#include <cuda_runtime.h>
#include <cuda_bf16.h>
#include <cstdint>
#include <math.h>

#define Bn 8
#define Cn 256
#define Nn 4096

#define L2E 1.4426950408889634f
#define C2  72.134752f        // 50 * log2(e)

// ---------------------------------------------------------------------------
// Scratch
// ---------------------------------------------------------------------------
__device__ __nv_bfloat16 g_xqh[(size_t)Bn * Nn * Cn];  // queries^T hi [B,N,C]
__device__ __nv_bfloat16 g_xql[(size_t)Bn * Nn * Cn];
__device__ __nv_bfloat16 g_xkh[(size_t)Bn * Nn * Cn];  // keys^T hi [B,N,C]
__device__ __nv_bfloat16 g_xkl[(size_t)Bn * Nn * Cn];
__device__ __nv_bfloat16 g_Mh[Cn * Cn];                // M = Wq^T Wk  [c][d]
__device__ __nv_bfloat16 g_Ml[Cn * Cn];
__device__ __nv_bfloat16 g_wvh[Cn * Cn];               // Wv hi [O,C]
__device__ __nv_bfloat16 g_wvl[Cn * Cn];
__device__ __nv_bfloat16 g_yh[(size_t)Bn * Nn * Cn];   // y = M xk  [B,N,C]
__device__ __nv_bfloat16 g_yl[(size_t)Bn * Nn * Cn];
__device__ __nv_bfloat16 g_vh[(size_t)Bn * Cn * Nn];   // v hi [B,C,N]
__device__ __nv_bfloat16 g_vl[(size_t)Bn * Cn * Nn];
__device__ __nv_bfloat16 g_Eh[(size_t)Bn * Nn * Nn];   // exp(s-50) bf16 [B,N,N]
__device__ float         g_Z [(size_t)Bn * Nn];        // row exp sums (exact fp32)
__device__ float         g_abw[513];                   // aw[256] | bw[256] | cc
__device__ float         g_alpha[(size_t)Bn * Nn];     // per-j bias (init 0)
__device__ float         g_beta [(size_t)Bn * Nn];     // per-i bias (init 0)

// ---------------------------------------------------------------------------
// Helpers
// ---------------------------------------------------------------------------
__device__ __forceinline__ uint32_t smem_u32(const void* p) {
    uint32_t a;
    asm("{ .reg .u64 t; cvta.to.shared.u64 t, %1; cvt.u32.u64 %0, t; }"
        : "=r"(a) : "l"(p));
    return a;
}

#define SMEM_SWIZZLE_64B(off) ((off) ^ (((off) >> 3) & 0x30))

__device__ __forceinline__ void ldmx4(uint32_t* r, uint32_t a) {
    asm volatile("ldmatrix.sync.aligned.m8n8.x4.shared.b16 {%0,%1,%2,%3}, [%4];"
        : "=r"(r[0]), "=r"(r[1]), "=r"(r[2]), "=r"(r[3]) : "r"(a));
}

__device__ __forceinline__ void mma16816(float* d, const uint32_t* a,
                                         uint32_t b0, uint32_t b1) {
    asm volatile(
        "mma.sync.aligned.m16n8k16.row.col.f32.bf16.bf16.f32 "
        "{%0,%1,%2,%3}, {%4,%5,%6,%7}, {%8,%9}, {%0,%1,%2,%3};"
        : "+f"(d[0]), "+f"(d[1]), "+f"(d[2]), "+f"(d[3])
        : "r"(a[0]), "r"(a[1]), "r"(a[2]), "r"(a[3]), "r"(b0), "r"(b1));
}

__device__ __forceinline__ float ex2f(float x) {
    float y;
    asm("ex2.approx.f32 %0, %1;" : "=f"(y) : "f"(x));
    return y;
}

__device__ __forceinline__ uint32_t pack2(float a, float b, float& ra, float& rb) {
    __nv_bfloat16 ah = __float2bfloat16_rn(a);
    __nv_bfloat16 bh = __float2bfloat16_rn(b);
    ra = a - __bfloat162float(ah);
    rb = b - __bfloat162float(bh);
    __nv_bfloat162 t = __halves2bfloat162(ah, bh);
    return *reinterpret_cast<uint32_t*>(&t);
}

__device__ __forceinline__ uint32_t pack2lo(float a, float b) {
    __nv_bfloat162 t = __halves2bfloat162(__float2bfloat16_rn(a),
                                          __float2bfloat16_rn(b));
    return *reinterpret_cast<uint32_t*>(&t);
}

// Packed convert: element a -> low half, b -> high half (one instruction).
__device__ __forceinline__ uint32_t cvt2bf(float a, float b) {
    uint32_t r;
    asm("cvt.rn.bf16x2.f32 %0, %1, %2;" : "=r"(r) : "f"(b), "f"(a));
    return r;
}

#define CP16(d, s) \
    asm volatile("cp.async.cg.shared.global [%0], [%1], 16;" :: "r"(d), "l"(s))
#define CP_COMMIT() asm volatile("cp.async.commit_group;" ::: "memory")
#define CP_WAIT1()  asm volatile("cp.async.wait_group 1;" ::: "memory")
#define CP_WAIT0()  asm volatile("cp.async.wait_group 0;" ::: "memory")

// ---------------------------------------------------------------------------
// GEMM building blocks.
// 4-tile stages (split x split): 3 x 32KB = 96KB.
// 3-tile stages (split x single, pv): 3 x 24KB = 72KB.
// ---------------------------------------------------------------------------
#define TILE_B   8192
#define STAGE_B  (4 * TILE_B)
#define NSTAGES  3
#define MMA_SMEM (NSTAGES * STAGE_B)
#define PV_STAGE_B (3 * TILE_B)
#define PV_SMEM  (NSTAGES * PV_STAGE_B)

__device__ __forceinline__ void cp_tile(uint32_t sdst, const __nv_bfloat16* g,
                                        int rs, int tid) {
    #pragma unroll
    for (int t = 0; t < 2; t++) {
        int u = tid + t * 256;
        int row = u >> 2, q = u & 3;
        uint32_t d = sdst + SMEM_SWIZZLE_64B((uint32_t)(row * 64 + q * 16));
        CP16(d, g + (size_t)row * rs + q * 8);
    }
}

__device__ __forceinline__ void prefetch4(uint32_t st,
                                          const __nv_bfloat16* ah,
                                          const __nv_bfloat16* al,
                                          const __nv_bfloat16* bh,
                                          const __nv_bfloat16* bl,
                                          int rsA, int rsB, int tid) {
    cp_tile(st + 0 * TILE_B, ah, rsA, tid);
    cp_tile(st + 1 * TILE_B, al, rsA, tid);
    cp_tile(st + 2 * TILE_B, bh, rsB, tid);
    cp_tile(st + 3 * TILE_B, bl, rsB, tid);
    CP_COMMIT();
}

__device__ __forceinline__ void prefetch3(uint32_t st,
                                          const __nv_bfloat16* ah,
                                          const __nv_bfloat16* al,
                                          const __nv_bfloat16* bh,
                                          int rsA, int rsB, int tid) {
    cp_tile(st + 0 * TILE_B, ah, rsA, tid);
    cp_tile(st + 1 * TILE_B, al, rsA, tid);
    cp_tile(st + 2 * TILE_B, bh, rsB, tid);
    CP_COMMIT();
}

// One K=32 chunk, 3-product split (hh+hl+lh).
__device__ __forceinline__ void chunk_mma(uint32_t tb, uint32_t aoff,
                                          uint32_t boff, uint32_t lsw,
                                          float acc[4][4][4]) {
    #pragma unroll
    for (int ks = 0; ks < 2; ks++) {
        uint32_t kb = (uint32_t)(ks * 32);
        uint32_t ah[4][4], al[4][4];
        #pragma unroll
        for (int it = 0; it < 4; it++) {
            uint32_t o = (aoff + it * 1024 + kb) ^ lsw;
            ldmx4(ah[it], tb + o);
            ldmx4(al[it], tb + TILE_B + o);
        }
        uint32_t bh[4][2], bl[4][2];
        #pragma unroll
        for (int jp = 0; jp < 2; jp++) {
            uint32_t o = (boff + jp * 1024 + kb) ^ lsw;
            uint32_t t4[4];
            ldmx4(t4, tb + 2 * TILE_B + o);
            bh[jp * 2][0]     = t4[0]; bh[jp * 2][1]     = t4[2];
            bh[jp * 2 + 1][0] = t4[1]; bh[jp * 2 + 1][1] = t4[3];
            ldmx4(t4, tb + 3 * TILE_B + o);
            bl[jp * 2][0]     = t4[0]; bl[jp * 2][1]     = t4[2];
            bl[jp * 2 + 1][0] = t4[1]; bl[jp * 2 + 1][1] = t4[3];
        }
        #pragma unroll
        for (int it = 0; it < 4; it++)
            #pragma unroll
            for (int nt = 0; nt < 4; nt++)
                mma16816(acc[it][nt], ah[it], bh[nt][0], bh[nt][1]);
        #pragma unroll
        for (int it = 0; it < 4; it++)
            #pragma unroll
            for (int nt = 0; nt < 4; nt++)
                mma16816(acc[it][nt], ah[it], bl[nt][0], bl[nt][1]);
        #pragma unroll
        for (int it = 0; it < 4; it++)
            #pragma unroll
            for (int nt = 0; nt < 4; nt++)
                mma16816(acc[it][nt], al[it], bh[nt][0], bh[nt][1]);
    }
}

// One K=32 chunk, 2-product (A split x B single: hh + lh).
__device__ __forceinline__ void chunk_mma_pv(uint32_t tb, uint32_t aoff,
                                             uint32_t boff, uint32_t lsw,
                                             float acc[4][4][4]) {
    #pragma unroll
    for (int ks = 0; ks < 2; ks++) {
        uint32_t kb = (uint32_t)(ks * 32);
        uint32_t ah[4][4], al[4][4];
        #pragma unroll
        for (int it = 0; it < 4; it++) {
            uint32_t o = (aoff + it * 1024 + kb) ^ lsw;
            ldmx4(ah[it], tb + o);
            ldmx4(al[it], tb + TILE_B + o);
        }
        uint32_t bh[4][2];
        #pragma unroll
        for (int jp = 0; jp < 2; jp++) {
            uint32_t o = (boff + jp * 1024 + kb) ^ lsw;
            uint32_t t4[4];
            ldmx4(t4, tb + 2 * TILE_B + o);
            bh[jp * 2][0]     = t4[0]; bh[jp * 2][1]     = t4[2];
            bh[jp * 2 + 1][0] = t4[1]; bh[jp * 2 + 1][1] = t4[3];
        }
        #pragma unroll
        for (int it = 0; it < 4; it++)
            #pragma unroll
            for (int nt = 0; nt < 4; nt++)
                mma16816(acc[it][nt], ah[it], bh[nt][0], bh[nt][1]);
        #pragma unroll
        for (int it = 0; it < 4; it++)
            #pragma unroll
            for (int nt = 0; nt < 4; nt++)
                mma16816(acc[it][nt], al[it], bh[nt][0], bh[nt][1]);
    }
}

// Plain 4-tile mainloop (scores).
__device__ __forceinline__ void mma_mainloop(
    uint32_t sbase,
    const __nv_bfloat16* Ah, const __nv_bfloat16* Al,
    const __nv_bfloat16* Bh, const __nv_bfloat16* Bl,
    int rsA, int rsB, int nch,
    float acc[4][4][4], int tid, int wid, int lane)
{
    const int iBase = (wid >> 2) * 64;
    const int jBase = (wid & 3) * 32;
    const uint32_t lsw  = (uint32_t)(((lane >> 1) & 3) * 16);
    const uint32_t aoff = (uint32_t)((iBase + (lane & 15)) * 64 + (lane >> 4) * 16);
    const uint32_t boff = (uint32_t)((jBase + (lane & 15)) * 64 + (lane >> 4) * 16);

    #pragma unroll
    for (int p = 0; p < 2; p++)
        prefetch4(sbase + p * STAGE_B, Ah + p * 32, Al + p * 32,
                  Bh + p * 32, Bl + p * 32, rsA, rsB, tid);

    int stage = 0;
    #pragma unroll 1
    for (int c = 0; c < nch; c++) {
        if (c + 1 < nch) CP_WAIT1(); else CP_WAIT0();
        __syncthreads();
        if (c + 2 < nch) {
            int ps = stage + 2; if (ps >= NSTAGES) ps -= NSTAGES;
            int ko = (c + 2) * 32;
            prefetch4(sbase + ps * STAGE_B, Ah + ko, Al + ko,
                      Bh + ko, Bl + ko, rsA, rsB, tid);
        }
        chunk_mma(sbase + stage * STAGE_B, aoff, boff, lsw, acc);
        if (++stage == NSTAGES) stage = 0;
    }
}

// 3-tile mainloop (pv: A split, B single).
__device__ __forceinline__ void mma_mainloop_pv(
    uint32_t sbase,
    const __nv_bfloat16* Ah, const __nv_bfloat16* Al,
    const __nv_bfloat16* Bh,
    int rsA, int rsB, int nch,
    float acc[4][4][4], int tid, int wid, int lane)
{
    const int iBase = (wid >> 2) * 64;
    const int jBase = (wid & 3) * 32;
    const uint32_t lsw  = (uint32_t)(((lane >> 1) & 3) * 16);
    const uint32_t aoff = (uint32_t)((iBase + (lane & 15)) * 64 + (lane >> 4) * 16);
    const uint32_t boff = (uint32_t)((jBase + (lane & 15)) * 64 + (lane >> 4) * 16);

    #pragma unroll
    for (int p = 0; p < 2; p++)
        prefetch3(sbase + p * PV_STAGE_B, Ah + p * 32, Al + p * 32,
                  Bh + p * 32, rsA, rsB, tid);

    int stage = 0;
    #pragma unroll 1
    for (int c = 0; c < nch; c++) {
        if (c + 1 < nch) CP_WAIT1(); else CP_WAIT0();
        __syncthreads();
        if (c + 2 < nch) {
            int ps = stage + 2; if (ps >= NSTAGES) ps -= NSTAGES;
            int ko = (c + 2) * 32;
            prefetch3(sbase + ps * PV_STAGE_B, Ah + ko, Al + ko,
                      Bh + ko, rsA, rsB, tid);
        }
        chunk_mma_pv(sbase + stage * PV_STAGE_B, aoff, boff, lsw, acc);
        if (++stage == NSTAGES) stage = 0;
    }
}

// ---------------------------------------------------------------------------
// Kernel B: ALL weight-derived precompute + zero-init, one launch.
// ---------------------------------------------------------------------------
__global__ void __launch_bounds__(256)
prep_kernel(const float* __restrict__ Wq, const float* __restrict__ Wk,
            const float* __restrict__ bq, const float* __restrict__ bk,
            const float* __restrict__ Wv) {
    const int bid = blockIdx.x, t = threadIdx.x;
    if (bid < 256) {
        const int c = bid;
        float a0 = 0.f, a1 = 0.f, a2 = 0.f, a3 = 0.f;
        #pragma unroll 4
        for (int o = 0; o < 256; o += 4) {
            a0 += Wq[(o + 0) * 256 + c] * Wk[(o + 0) * 256 + t];
            a1 += Wq[(o + 1) * 256 + c] * Wk[(o + 1) * 256 + t];
            a2 += Wq[(o + 2) * 256 + c] * Wk[(o + 2) * 256 + t];
            a3 += Wq[(o + 3) * 256 + c] * Wk[(o + 3) * 256 + t];
        }
        float acc = (a0 + a1) + (a2 + a3);
        __nv_bfloat16 h = __float2bfloat16_rn(acc);
        g_Mh[c * 256 + t] = h;
        g_Ml[c * 256 + t] = __float2bfloat16_rn(acc - __bfloat162float(h));
    } else if (bid == 256) {
        float a0 = 0.f, a1 = 0.f;
        #pragma unroll 4
        for (int o = 0; o < 256; o += 2) {
            a0 += Wk[(o + 0) * 256 + t] * bq[o + 0];
            a1 += Wk[(o + 1) * 256 + t] * bq[o + 1];
        }
        g_abw[t] = a0 + a1;
    } else if (bid == 257) {
        float a0 = 0.f, a1 = 0.f;
        #pragma unroll 4
        for (int o = 0; o < 256; o += 2) {
            a0 += Wq[(o + 0) * 256 + t] * bk[o + 0];
            a1 += Wq[(o + 1) * 256 + t] * bk[o + 1];
        }
        g_abw[256 + t] = a0 + a1;
    } else if (bid == 258) {
        if (t < 32) {
            float s = 0.f;
            for (int o = t; o < 256; o += 32) s += bq[o] * bk[o];
            #pragma unroll
            for (int off = 16; off; off >>= 1)
                s += __shfl_xor_sync(0xffffffffu, s, off);
            if (t == 0) g_abw[512] = s;
        }
    } else if (bid < 515) {
        int idx = (bid - 259) * 256 + t;
        float f = Wv[idx];
        __nv_bfloat16 h = __float2bfloat16_rn(f);
        g_wvh[idx] = h;
        g_wvl[idx] = __float2bfloat16_rn(f - __bfloat162float(h));
    } else if (bid < 643) {
        g_Z[(size_t)(bid - 515) * 256 + t] = 0.f;
    } else if (bid < 771) {
        g_alpha[(size_t)(bid - 643) * 256 + t] = 0.f;
    } else {
        g_beta[(size_t)(bid - 771) * 256 + t] = 0.f;
    }
}

// ---------------------------------------------------------------------------
// Kernel A: transpose + bf16 hi/lo split + fused dot accumulation.
// ---------------------------------------------------------------------------
__global__ void __launch_bounds__(256)
conv_split(const float* __restrict__ queries, const float* __restrict__ keys) {
    __shared__ float ts[32][33];
    const int z = blockIdx.z;
    const int which = z >> 3, b = z & 7;
    const int c0 = blockIdx.y * 32, n0 = blockIdx.x * 32;
    const int r = threadIdx.x >> 5, col = threadIdx.x & 31;

    const float* x = which ? keys : queries;
    __nv_bfloat16* oh = which ? g_xkh : g_xqh;
    __nv_bfloat16* ol = which ? g_xkl : g_xql;
    const float* w = g_abw + (which ? 0 : 256);
    float* dotout = which ? g_alpha : g_beta;

    const float* xb = x + ((size_t)b * Cn + c0) * Nn + n0;
    #pragma unroll
    for (int p = 0; p < 4; p++)
        ts[r + p * 8][col] = xb[(size_t)(r + p * 8) * Nn + col];
    __syncthreads();

    __nv_bfloat16* dh = oh + ((size_t)b * Nn + n0) * Cn + c0;
    __nv_bfloat16* dl = ol + ((size_t)b * Nn + n0) * Cn + c0;
    #pragma unroll
    for (int p = 0; p < 4; p++) {
        int n = r + p * 8;
        float f = ts[col][n];
        __nv_bfloat16 h = __float2bfloat16_rn(f);
        dh[(size_t)n * Cn + col] = h;
        dl[(size_t)n * Cn + col] = __float2bfloat16_rn(f - __bfloat162float(h));
    }

    const float wv = w[c0 + col];
    #pragma unroll
    for (int p = 0; p < 4; p++) {
        int n = r + p * 8;
        float s = ts[col][n] * wv;
        #pragma unroll
        for (int off = 16; off; off >>= 1)
            s += __shfl_xor_sync(0xffffffffu, s, off);
        if (col == 0)
            atomicAdd(&dotout[(size_t)b * Nn + n0 + n], s);
    }
}

// ---------------------------------------------------------------------------
// Kernel C: merged projection GEMMs, one launch. Grid (32, 1, 16).
// z < 8:  y = M xk  -> [N, C], chained over 2 o-tiles, no bias.
// z >= 8: v = Wv xk -> [C, N], chained over 2 n-tiles, bias bv.
// ---------------------------------------------------------------------------
__global__ void __launch_bounds__(256, 2)
proj_both(const float* __restrict__ bv) {
    extern __shared__ char smem[];
    uint32_t sbase = smem_u32(smem);
    const int tid = threadIdx.x;
    const int wid = tid >> 5, lane = tid & 31;

    const int iBase = (wid >> 2) * 64;
    const int jBase = (wid & 3) * 32;
    const uint32_t lsw  = (uint32_t)(((lane >> 1) & 3) * 16);
    const uint32_t aoff = (uint32_t)((iBase + (lane & 15)) * 64 + (lane >> 4) * 16);
    const uint32_t boff = (uint32_t)((jBase + (lane & 15)) * 64 + (lane >> 4) * 16);
    const int g_ = lane >> 2, cp2 = (lane & 3) * 2;

    float acc[4][4][4] = {};
    const int G = 16;

    if (blockIdx.z < 8) {
        const int b  = blockIdx.z;
        const int n0 = blockIdx.x * 128;
        const __nv_bfloat16* Ah = g_xkh + ((size_t)b * Nn + n0) * Cn;
        const __nv_bfloat16* Al = g_xkl + ((size_t)b * Nn + n0) * Cn;
        __nv_bfloat16* dh = g_yh + (size_t)b * Nn * Cn;
        __nv_bfloat16* dl = g_yl + (size_t)b * Nn * Cn;

        #pragma unroll
        for (int p = 0; p < 2; p++)
            prefetch4(sbase + p * STAGE_B, Ah + p * 32, Al + p * 32,
                      g_Mh + p * 32, g_Ml + p * 32, Cn, Cn, tid);

        int stage = 0;
        #pragma unroll 1
        for (int g = 0; g < G; g++) {
            if (g + 1 < G) CP_WAIT1(); else CP_WAIT0();
            __syncthreads();
            if (g + 2 < G) {
                int ps = stage + 2; if (ps >= NSTAGES) ps -= NSTAGES;
                int gg = g + 2;
                int kc = (gg & 7) * 32;
                size_t bo = (size_t)(gg >> 3) * 128 * Cn + kc;
                prefetch4(sbase + ps * STAGE_B, Ah + kc, Al + kc,
                          g_Mh + bo, g_Ml + bo, Cn, Cn, tid);
            }
            chunk_mma(sbase + stage * STAGE_B, aoff, boff, lsw, acc);
            if (++stage == NSTAGES) stage = 0;

            if ((g & 7) == 7) {
                int o0 = (g >> 3) * 128;
                #pragma unroll
                for (int nt = 0; nt < 4; nt++) {
                    int cc = o0 + jBase + nt * 8 + cp2;
                    #pragma unroll
                    for (int it = 0; it < 4; it++) {
                        int r1 = n0 + iBase + it * 16 + g_;
                        float l0, l1;
                        uint32_t h01 = pack2(acc[it][nt][0], acc[it][nt][1], l0, l1);
                        *reinterpret_cast<uint32_t*>(&dh[(size_t)r1 * Cn + cc]) = h01;
                        *reinterpret_cast<uint32_t*>(&dl[(size_t)r1 * Cn + cc]) = pack2lo(l0, l1);
                        uint32_t h23 = pack2(acc[it][nt][2], acc[it][nt][3], l0, l1);
                        *reinterpret_cast<uint32_t*>(&dh[(size_t)(r1 + 8) * Cn + cc]) = h23;
                        *reinterpret_cast<uint32_t*>(&dl[(size_t)(r1 + 8) * Cn + cc]) = pack2lo(l0, l1);
                    }
                }
                #pragma unroll
                for (int it = 0; it < 4; it++)
                    #pragma unroll
                    for (int nt = 0; nt < 4; nt++)
                        #pragma unroll
                        for (int k = 0; k < 4; k++)
                            acc[it][nt][k] = 0.f;
            }
        }
    } else {
        const int b   = blockIdx.z - 8;
        const int o0  = (blockIdx.x >> 4) * 128;
        const int n00 = (blockIdx.x & 15) * 256;
        const __nv_bfloat16* Ah = g_wvh + (size_t)o0 * Cn;
        const __nv_bfloat16* Al = g_wvl + (size_t)o0 * Cn;
        const __nv_bfloat16* Bh0 = g_xkh + ((size_t)b * Nn + n00) * Cn;
        const __nv_bfloat16* Bl0 = g_xkl + ((size_t)b * Nn + n00) * Cn;
        __nv_bfloat16* dh = g_vh + (size_t)b * Cn * Nn;
        __nv_bfloat16* dl = g_vl + (size_t)b * Cn * Nn;

        #pragma unroll
        for (int p = 0; p < 2; p++)
            prefetch4(sbase + p * STAGE_B, Ah + p * 32, Al + p * 32,
                      Bh0 + p * 32, Bl0 + p * 32, Cn, Cn, tid);

        int stage = 0;
        #pragma unroll 1
        for (int g = 0; g < G; g++) {
            if (g + 1 < G) CP_WAIT1(); else CP_WAIT0();
            __syncthreads();
            if (g + 2 < G) {
                int ps = stage + 2; if (ps >= NSTAGES) ps -= NSTAGES;
                int gg = g + 2;
                int kc = (gg & 7) * 32;
                size_t bo = (size_t)(gg >> 3) * 128 * Cn + kc;
                prefetch4(sbase + ps * STAGE_B, Ah + kc, Al + kc,
                          Bh0 + bo, Bl0 + bo, Cn, Cn, tid);
            }
            chunk_mma(sbase + stage * STAGE_B, aoff, boff, lsw, acc);
            if (++stage == NSTAGES) stage = 0;

            if ((g & 7) == 7) {
                int n0 = n00 + (g >> 3) * 128;
                #pragma unroll
                for (int it = 0; it < 4; it++) {
                    int r1 = o0 + iBase + it * 16 + g_;
                    float br1 = bv[r1], br2 = bv[r1 + 8];
                    #pragma unroll
                    for (int nt = 0; nt < 4; nt++) {
                        int cc = n0 + jBase + nt * 8 + cp2;
                        float l0, l1;
                        uint32_t h01 = pack2(acc[it][nt][0] + br1, acc[it][nt][1] + br1, l0, l1);
                        *reinterpret_cast<uint32_t*>(&dh[(size_t)r1 * Nn + cc]) = h01;
                        *reinterpret_cast<uint32_t*>(&dl[(size_t)r1 * Nn + cc]) = pack2lo(l0, l1);
                        uint32_t h23 = pack2(acc[it][nt][2] + br2, acc[it][nt][3] + br2, l0, l1);
                        *reinterpret_cast<uint32_t*>(&dh[(size_t)(r1 + 8) * Nn + cc]) = h23;
                        *reinterpret_cast<uint32_t*>(&dl[(size_t)(r1 + 8) * Nn + cc]) = pack2lo(l0, l1);
                    }
                }
                #pragma unroll
                for (int it = 0; it < 4; it++)
                    #pragma unroll
                    for (int nt = 0; nt < 4; nt++)
                        #pragma unroll
                        for (int k = 0; k < 4; k++)
                            acc[it][nt][k] = 0.f;
            }
        }
    }
}

// ---------------------------------------------------------------------------
// Kernel D: scores = xq . y + beta_i + alpha_j + cc, masked.
// Stores E = exp(s-50) as SINGLE bf16 (packed cvt) + exact fp32 Z sums.
// ---------------------------------------------------------------------------
__global__ void __launch_bounds__(256, 2)
scores_mma(const float* __restrict__ mask) {
    extern __shared__ char smem[];
    uint32_t sbase = smem_u32(smem);
    const int tid = threadIdx.x;
    const int wid = tid >> 5, lane = tid & 31;

    const int b  = blockIdx.z;
    const int i0 = blockIdx.y * 128;
    const int j0 = blockIdx.x * 128;

    float acc[4][4][4] = {};
    mma_mainloop(sbase,
                 g_xqh + ((size_t)b * Nn + i0) * Cn, g_xql + ((size_t)b * Nn + i0) * Cn,
                 g_yh  + ((size_t)b * Nn + j0) * Cn, g_yl  + ((size_t)b * Nn + j0) * Cn,
                 Cn, Cn, Cn / 32, acc, tid, wid, lane);

    const int iBase = (wid >> 2) * 64;
    const int jBase = (wid & 3) * 32;
    const int g = lane >> 2, cp2 = (lane & 3) * 2;
    const float* mb = mask + (size_t)b * Nn;
    const float* Ab = g_alpha + (size_t)b * Nn;
    const float* Bt = g_beta  + (size_t)b * Nn;
    const float ccv = g_abw[512];
    __nv_bfloat16* Ehb = g_Eh + (size_t)b * Nn * Nn;
    float* Zb = g_Z + (size_t)b * Nn;

    float a0[4], a1[4];
    #pragma unroll
    for (int nt = 0; nt < 4; nt++) {
        int cc = j0 + jBase + nt * 8 + cp2;
        a0[nt] = Ab[cc];
        a1[nt] = Ab[cc + 1];
    }

    #pragma unroll
    for (int it = 0; it < 4; it++) {
        int r1 = i0 + iBase + it * 16 + g;
        float m1 = mb[r1], m2 = mb[r1 + 8];
        float bi1 = Bt[r1] + ccv, bi2 = Bt[r1 + 8] + ccv;
        float z1 = 0.f, z2 = 0.f;
        #pragma unroll
        for (int nt = 0; nt < 4; nt++) {
            int cc = j0 + jBase + nt * 8 + cp2;
            float e0 = ex2f(fmaf((acc[it][nt][0] + bi1 + a0[nt]) * m1, L2E, -C2));
            float e1 = ex2f(fmaf((acc[it][nt][1] + bi1 + a1[nt]) * m1, L2E, -C2));
            float e2 = ex2f(fmaf((acc[it][nt][2] + bi2 + a0[nt]) * m2, L2E, -C2));
            float e3 = ex2f(fmaf((acc[it][nt][3] + bi2 + a1[nt]) * m2, L2E, -C2));
            z1 += e0 + e1;
            z2 += e2 + e3;
            *reinterpret_cast<uint32_t*>(&Ehb[(size_t)r1 * Nn + cc])       = cvt2bf(e0, e1);
            *reinterpret_cast<uint32_t*>(&Ehb[(size_t)(r1 + 8) * Nn + cc]) = cvt2bf(e2, e3);
        }
        z1 += __shfl_xor_sync(0xffffffffu, z1, 1);
        z1 += __shfl_xor_sync(0xffffffffu, z1, 2);
        z2 += __shfl_xor_sync(0xffffffffu, z2, 1);
        z2 += __shfl_xor_sync(0xffffffffu, z2, 2);
        if ((lane & 3) == 0) {
            atomicAdd(&Zb[r1], z1);
            atomicAdd(&Zb[r1 + 8], z2);
        }
    }
}

// ---------------------------------------------------------------------------
// Kernel E: PV GEMM (V split x E single) + normalize/blend epilogue.
// ---------------------------------------------------------------------------
__global__ void __launch_bounds__(256, 2)
pv_mma(const float* __restrict__ mask,
       const float* __restrict__ queries,
       float* __restrict__ out) {
    extern __shared__ char smem[];
    uint32_t sbase = smem_u32(smem);
    const int tid = threadIdx.x;
    const int wid = tid >> 5, lane = tid & 31;

    const int b  = blockIdx.z;
    const int c0 = blockIdx.y * 128;
    const int q0 = blockIdx.x * 128;

    float acc[4][4][4] = {};
    mma_mainloop_pv(sbase,
                    g_vh + ((size_t)b * Cn + c0) * Nn, g_vl + ((size_t)b * Cn + c0) * Nn,
                    g_Eh + ((size_t)b * Nn + q0) * Nn,
                    Nn, Nn, Nn / 32, acc, tid, wid, lane);

    const int iBase = (wid >> 2) * 64;
    const int jBase = (wid & 3) * 32;
    const int g = lane >> 2, cp2 = (lane & 3) * 2;
    const float* mb = mask + (size_t)b * Nn;
    const float* Zb = g_Z + (size_t)b * Nn;

    int   qc[4];
    float m0[4], m1[4], iz0[4], iz1[4];
    #pragma unroll
    for (int nt = 0; nt < 4; nt++) {
        qc[nt] = q0 + jBase + nt * 8 + cp2;
        m0[nt] = mb[qc[nt]];
        m1[nt] = mb[qc[nt] + 1];
        iz0[nt] = __fdividef(1.f, Zb[qc[nt]]);
        iz1[nt] = __fdividef(1.f, Zb[qc[nt] + 1]);
    }

    #pragma unroll
    for (int it = 0; it < 4; it++) {
        int cr = c0 + iBase + it * 16 + g;
        #pragma unroll
        for (int nt = 0; nt < 4; nt++) {
            size_t gi1 = ((size_t)b * Cn + cr) * Nn + qc[nt];
            size_t gi2 = gi1 + (size_t)8 * Nn;
            float2 qa = *reinterpret_cast<const float2*>(&queries[gi1]);
            float2 qb = *reinterpret_cast<const float2*>(&queries[gi2]);
            float2 o1, o2;
            o1.x = qa.x * m0[nt] + (1.f - m0[nt]) * acc[it][nt][0] * iz0[nt];
            o1.y = qa.y * m1[nt] + (1.f - m1[nt]) * acc[it][nt][1] * iz1[nt];
            o2.x = qb.x * m0[nt] + (1.f - m0[nt]) * acc[it][nt][2] * iz0[nt];
            o2.y = qb.y * m1[nt] + (1.f - m1[nt]) * acc[it][nt][3] * iz1[nt];
            *reinterpret_cast<float2*>(&out[gi1]) = o1;
            *reinterpret_cast<float2*>(&out[gi2]) = o2;
        }
    }
}

// ---------------------------------------------------------------------------
// Launch
// ---------------------------------------------------------------------------
extern "C" void kernel_launch(void* const* d_in, const int* in_sizes, int n_in,
                              void* d_out, int out_size) {
    const float* queries = (const float*)d_in[0];
    const float* keys    = (const float*)d_in[1];
    const float* mask    = (const float*)d_in[2];
    const float* Wq      = (const float*)d_in[3];
    const float* bq      = (const float*)d_in[4];
    const float* Wk      = (const float*)d_in[5];
    const float* bk      = (const float*)d_in[6];
    const float* Wv      = (const float*)d_in[7];
    const float* bv      = (const float*)d_in[8];
    float* out = (float*)d_out;

    cudaFuncSetAttribute(proj_both,  cudaFuncAttributeMaxDynamicSharedMemorySize, MMA_SMEM);
    cudaFuncSetAttribute(scores_mma, cudaFuncAttributeMaxDynamicSharedMemorySize, MMA_SMEM);
    cudaFuncSetAttribute(pv_mma,     cudaFuncAttributeMaxDynamicSharedMemorySize, PV_SMEM);

    // All weight-derived precompute + zero-init in one launch.
    prep_kernel<<<899, 256>>>(Wq, Wk, bq, bk, Wv);

    // Input transpose + split + alpha/beta dots (merged q+k launch).
    dim3 gcv(Nn / 32, Cn / 32, 2 * Bn);
    conv_split<<<gcv, 256>>>(queries, keys);

    // Merged projection GEMMs: y = M xk and v = Wv xk in one launch.
    dim3 gpj(32, 1, 16);
    proj_both<<<gpj, 256, MMA_SMEM>>>(bv);

    // Scores -> E (single bf16) + exact Z
    dim3 gsc(Nn / 128, Nn / 128, Bn);
    scores_mma<<<gsc, 256, MMA_SMEM>>>(mask);

    // PV (2-product) + normalize + blend
    dim3 gpv(Nn / 128, Cn / 128, Bn);
    pv_mma<<<gpv, 256, PV_SMEM>>>(mask, queries, out);
}